// round 15
// baseline (speedup 1.0000x reference)
#include <cuda_runtime.h>
#include <cuda_bf16.h>
#include <math.h>
#include <stdint.h>

#define NB    64
#define DIMX  4096
#define HEADS 32
#define HDIM  192
#define RDIM  64
#define QLRK  1536
#define OLRK  512
#define GRP   8
#define BS    64
#define MAXB  64
#define LMAX  4096
#define TOPKK 1024
#define EPSI  1e-6f
#define NEGF  -1e30f
#define QDIM  (HEADS*HDIM)   /* 6144 */
#define SCALE_F 0.07216878364870323f  /* 192^-0.5 */

/* disjoint split-K partial regions (floats) */
#define PART_QA_OFF 0                         /* 16*98304  = 1572864 */
#define PART_KV_OFF 1572864                   /* 32*12288  = 393216  */
#define PART_QB_OFF 1966080                   /* 6*393216  = 2359296 */
#define PART_TOTAL  4325376                   /* 16.5 MB */

/* ------------------------------------------------------------------ */
/* scratch                                                            */
/* ------------------------------------------------------------------ */
__device__ __nv_bfloat16 g_xhi[NB*DIMX];
__device__ __nv_bfloat16 g_xlo[NB*DIMX];
__device__ __nv_bfloat16 g_qahi[NB*QLRK];
__device__ __nv_bfloat16 g_qalo[NB*QLRK];
__device__ float g_kv[NB*HDIM];
__device__ __nv_bfloat16 g_qhi[NB*QDIM];
__device__ __nv_bfloat16 g_qlo[NB*QDIM];
__device__ float g_logits[(size_t)NB*HEADS*LMAX];       /* 32 MB */
__device__ float g_tau[NB*HEADS];
__device__ float g_mrow[NB*HEADS];
__device__ float g_invden[NB*HEADS];
__device__ float g_opart[(size_t)4*NB*HEADS*HDIM];      /* 6.3 MB */
__device__ __nv_bfloat16 g_oohi[NB*QDIM];
__device__ __nv_bfloat16 g_oolo[NB*QDIM];
__device__ __nv_bfloat16 g_lathi[NB*GRP*OLRK];
__device__ __nv_bfloat16 g_latlo[NB*GRP*OLRK];
__device__ float g_part[PART_TOTAL];

/* ------------------------------------------------------------------ */
/* helpers                                                            */
/* ------------------------------------------------------------------ */
__device__ __forceinline__ uint32_t smem_u32(const void* p){
    uint32_t a;
    asm("{ .reg .u64 t; cvta.to.shared.u64 t, %1; cvt.u32.u64 %0, t; }"
        : "=r"(a) : "l"(p));
    return a;
}
__device__ __forceinline__ uint32_t sw128(uint32_t b){ return b ^ ((b >> 3) & 0x70); }

/* fast exact split: hi = truncate-to-bf16 (bit prefix), lo = rn(v-hi). */
__device__ __forceinline__ void split2(float x, float y, uint32_t& hp, uint32_t& lp){
    uint32_t bx = __float_as_uint(x), by = __float_as_uint(y);
    uint32_t h;
    asm("prmt.b32 %0, %1, %2, 0x7632;" : "=r"(h) : "r"(bx), "r"(by));
    float fx = __uint_as_float(h << 16);
    float fy = __uint_as_float(h & 0xFFFF0000u);
    float lx = x - fx, ly = y - fy;
    uint32_t l;
    asm("cvt.rn.bf16x2.f32 %0, %1, %2;" : "=r"(l) : "f"(ly), "f"(lx));
    hp = h; lp = l;
}
__device__ __forceinline__ void mma16816(float* c, const uint32_t* a, const uint32_t* b){
    asm volatile("mma.sync.aligned.m16n8k16.row.col.f32.bf16.bf16.f32 "
        "{%0,%1,%2,%3}, {%4,%5,%6,%7}, {%8,%9}, {%0,%1,%2,%3};"
        : "+f"(c[0]), "+f"(c[1]), "+f"(c[2]), "+f"(c[3])
        : "r"(a[0]), "r"(a[1]), "r"(a[2]), "r"(a[3]), "r"(b[0]), "r"(b[1]));
}
__device__ __forceinline__ void ldm_x4(uint32_t* r, uint32_t addr){
    asm volatile("ldmatrix.sync.aligned.m8n8.x4.shared.b16 {%0,%1,%2,%3}, [%4];"
        : "=r"(r[0]), "=r"(r[1]), "=r"(r[2]), "=r"(r[3]) : "r"(addr));
}
__device__ __forceinline__ void ldm_x4t(uint32_t* r, uint32_t addr){
    asm volatile("ldmatrix.sync.aligned.m8n8.x4.trans.shared.b16 {%0,%1,%2,%3}, [%4];"
        : "=r"(r[0]), "=r"(r[1]), "=r"(r[2]), "=r"(r[3]) : "r"(addr));
}
__device__ __forceinline__ void cvt_store(char* hiB, char* loB, uint32_t off, float4 v){
    uint2 hh, ll;
    split2(v.x, v.y, hh.x, ll.x);
    split2(v.z, v.w, hh.y, ll.y);
    *(uint2*)(hiB + off) = hh;
    *(uint2*)(loB + off) = ll;
}

/* ------------------------------------------------------------------ */
/* HMMA GEMM (round-12 best config: single stage, warp tile 32x32)    */
/* ------------------------------------------------------------------ */
#define MM_SMEM 49152
__global__ void __launch_bounds__(256,2) k_gemm_mma(
    const __nv_bfloat16* __restrict__ Xhi, const __nv_bfloat16* __restrict__ Xlo,
    int ldx, long long xGrp,
    const float* __restrict__ W, int ldw, long long wGrp,
    float* __restrict__ C, int ldc, long long cGrp, long long cSplit,
    int Kloc, int Nw)
{
    extern __shared__ char sm[];
    char* sXhi = sm;
    char* sXlo = sm + 8192;
    char* sWhi = sm + 16384;
    char* sWlo = sm + 32768;
    uint32_t smb = smem_u32(sm);

    int tid = threadIdx.x, wid = tid >> 5, lane = tid & 31;
    int n0 = blockIdx.x * 128;
    int s  = blockIdx.y;
    int g  = blockIdx.z;
    Xhi += (size_t)g * xGrp + (size_t)s * Kloc;
    Xlo += (size_t)g * xGrp + (size_t)s * Kloc;
    W   += (size_t)g * wGrp + (size_t)s * Kloc;
    C   += (size_t)g * cGrp + (size_t)s * cSplit;

    int wm = (wid & 1) * 32;
    int wn = (wid >> 1) * 32;

    float acc[8][4];
#pragma unroll
    for (int i = 0; i < 8; i++)
#pragma unroll
        for (int j = 0; j < 4; j++) acc[i][j] = 0.f;

    int xr0 = tid >> 3, xr1 = (tid + 256) >> 3;
    int xc16 = tid & 7;
    int wrow = tid >> 1;
    int wc   = tid & 1;
    int wrg  = n0 + wrow; if (wrg >= Nw) wrg = Nw - 1;

    const int NC = Kloc / 64;
    uint4 xh[2], xl[2];
    float4 wv[8];
    xh[0] = *(const uint4*)(Xhi + (size_t)xr0 * ldx + xc16 * 8);
    xh[1] = *(const uint4*)(Xhi + (size_t)xr1 * ldx + xc16 * 8);
    xl[0] = *(const uint4*)(Xlo + (size_t)xr0 * ldx + xc16 * 8);
    xl[1] = *(const uint4*)(Xlo + (size_t)xr1 * ldx + xc16 * 8);
#pragma unroll
    for (int j = 0; j < 8; j++)
        wv[j] = *(const float4*)(W + (size_t)wrg * ldw + (wc + 2*j) * 4);

    for (int ch = 0; ch < NC; ch++) {
        if (ch) __syncthreads();
        {
            uint32_t o0 = sw128((uint32_t)(xr0 * 128 + xc16 * 16));
            uint32_t o1 = sw128((uint32_t)(xr1 * 128 + xc16 * 16));
            *(uint4*)(sXhi + o0) = xh[0];
            *(uint4*)(sXhi + o1) = xh[1];
            *(uint4*)(sXlo + o0) = xl[0];
            *(uint4*)(sXlo + o1) = xl[1];
        }
#pragma unroll
        for (int j = 0; j < 8; j++) {
            uint32_t off = sw128((uint32_t)(wrow * 128 + (wc + 2*j) * 8));
            cvt_store(sWhi, sWlo, off, wv[j]);
        }
        __syncthreads();
        if (ch + 1 < NC) {
            int kb = (ch + 1) * 64;
            xh[0] = *(const uint4*)(Xhi + (size_t)xr0 * ldx + kb + xc16 * 8);
            xh[1] = *(const uint4*)(Xhi + (size_t)xr1 * ldx + kb + xc16 * 8);
            xl[0] = *(const uint4*)(Xlo + (size_t)xr0 * ldx + kb + xc16 * 8);
            xl[1] = *(const uint4*)(Xlo + (size_t)xr1 * ldx + kb + xc16 * 8);
#pragma unroll
            for (int j = 0; j < 8; j++)
                wv[j] = *(const float4*)(W + (size_t)wrg * ldw + kb + (wc + 2*j) * 4);
        }
#pragma unroll
        for (int ks = 0; ks < 4; ks++) {
            uint32_t ah[2][4], al[2][4];
#pragma unroll
            for (int mtq = 0; mtq < 2; mtq++) {
                int arow = wm + mtq * 16 + (lane & 15);
                uint32_t aoff = sw128((uint32_t)(arow * 128 + (ks*2 + (lane >> 4)) * 16));
                ldm_x4(ah[mtq], smb + aoff);
                ldm_x4(al[mtq], smb + 8192 + aoff);
            }
#pragma unroll
            for (int t = 0; t < 2; t++) {
                int brow = wn + 16*t + ((lane >> 4) & 1) * 8 + (lane & 7);
                uint32_t boff = sw128((uint32_t)(brow * 128 + (ks*2 + ((lane >> 3) & 1)) * 16));
                uint32_t bh[4], bl[4];
                ldm_x4(bh, smb + 16384 + boff);
                ldm_x4(bl, smb + 32768 + boff);
#pragma unroll
                for (int mtq = 0; mtq < 2; mtq++) {
                    float* a0 = acc[mtq*4 + t*2];
                    float* a1 = acc[mtq*4 + t*2 + 1];
                    mma16816(a0, ah[mtq], bh);
                    mma16816(a0, ah[mtq], bl);
                    mma16816(a0, al[mtq], bh);
                    mma16816(a1, ah[mtq], bh + 2);
                    mma16816(a1, ah[mtq], bl + 2);
                    mma16816(a1, al[mtq], bh + 2);
                }
            }
        }
    }

#pragma unroll
    for (int mtq = 0; mtq < 2; mtq++) {
        int mr = wm + mtq * 16 + (lane >> 2);
#pragma unroll
        for (int sub = 0; sub < 4; sub++) {
            int nc = n0 + wn + sub * 8 + (lane & 3) * 2;
            float* a = acc[mtq*4 + sub];
            if (nc < Nw) {
                C[(size_t)mr * ldc + nc]       = a[0];
                C[(size_t)(mr + 8) * ldc + nc] = a[2];
            }
            if (nc + 1 < Nw) {
                C[(size_t)mr * ldc + nc + 1]       = a[1];
                C[(size_t)(mr + 8) * ldc + nc + 1] = a[3];
            }
        }
    }
}

/* generic split-K reduce -> fp32 */
__global__ void k_reduce(const float* __restrict__ part, float* __restrict__ out,
                         int E, int S)
{
    int i = blockIdx.x * 256 + threadIdx.x;
    if (i >= E) return;
    float s = 0.f;
    for (int p = 0; p < S; p++) s += part[(size_t)p * E + i];
    out[i] = s;
}

/* split-K reduce -> bf16 hi/lo pairs */
__global__ void k_reduce_bf(const float* __restrict__ part,
                            __nv_bfloat16* __restrict__ ohi,
                            __nv_bfloat16* __restrict__ olo,
                            int Epairs, int E, int S)
{
    int p = blockIdx.x * 256 + threadIdx.x;
    if (p >= Epairs) return;
    int e0 = 2 * p;
    float v0 = 0.f, v1 = 0.f;
    for (int q = 0; q < S; q++) {
        v0 += part[(size_t)q * E + e0];
        v1 += part[(size_t)q * E + e0 + 1];
    }
    uint32_t hp, lp;
    split2(v0, v1, hp, lp);
    ((uint32_t*)ohi)[p] = hp;
    ((uint32_t*)olo)[p] = lp;
}

/* x fp32 -> bf16 hi/lo */
__global__ void __launch_bounds__(256) k_x2bf(const float* __restrict__ x,
                                              __nv_bfloat16* __restrict__ xhi,
                                              __nv_bfloat16* __restrict__ xlo)
{
    int p = blockIdx.x * 256 + threadIdx.x;
    float2 v = ((const float2*)x)[p];
    uint32_t hp, lp;
    split2(v.x, v.y, hp, lp);
    ((uint32_t*)xhi)[p] = hp;
    ((uint32_t*)xlo)[p] = lp;
}

/* ------------------------------------------------------------------ */
/* fused: reduce 16 partials + RMS(q_norm) -> bf16 hi/lo              */
/* ------------------------------------------------------------------ */
__global__ void __launch_bounds__(256) k_fuse_qa(const float* __restrict__ part,
                                                 const float* __restrict__ wt,
                                                 __nv_bfloat16* __restrict__ qahi,
                                                 __nv_bfloat16* __restrict__ qalo)
{
    __shared__ float red[256];
    int n = blockIdx.x, tid = threadIdx.x;
    float v0[3], v1[3]; float s = 0.f;
#pragma unroll
    for (int i = 0; i < 3; i++) {
        int e0 = 2 * (tid + i*256);
        float a = 0.f, b = 0.f;
#pragma unroll
        for (int p = 0; p < 16; p++) {
            a += part[(size_t)p*NB*QLRK + (size_t)n*QLRK + e0];
            b += part[(size_t)p*NB*QLRK + (size_t)n*QLRK + e0 + 1];
        }
        v0[i] = a; v1[i] = b; s += a*a + b*b;
    }
    red[tid] = s; __syncthreads();
    for (int k = 128; k > 0; k >>= 1) { if (tid < k) red[tid] += red[tid+k]; __syncthreads(); }
    float scale = rsqrtf(red[0] / (float)QLRK + EPSI);
#pragma unroll
    for (int i = 0; i < 3; i++) {
        int p = tid + i*256;
        int e0 = 2 * p;
        float f0 = v0[i] * scale * wt[e0];
        float f1 = v1[i] * scale * wt[e0 + 1];
        uint32_t hp, lp;
        split2(f0, f1, hp, lp);
        ((uint32_t*)qahi)[(size_t)n*(QLRK/2) + p] = hp;
        ((uint32_t*)qalo)[(size_t)n*(QLRK/2) + p] = lp;
    }
}

__device__ __forceinline__ void rope_cs(int i, float pos, float& c, float& s)
{
    float inv = (float)exp(-(double)i * 0.28782313662425574); /* ln(1e4)/32 */
    float ang = pos * inv;
    double ad = (double)ang;
    c = (float)cos(ad); s = (float)sin(ad);
}

/* fused: reduce 32 partials + RMS + rope -> g_kv (fp32)              */
__global__ void k_fuse_kv(const float* __restrict__ part,
                          const float* __restrict__ wt,
                          const int* __restrict__ ctxl,
                          float* __restrict__ kv)
{
    __shared__ float srow[HDIM];
    __shared__ float rs[64];
    int n = blockIdx.x, tid = threadIdx.x;
    float s = 0.f;
#pragma unroll
    for (int j = 0; j < 3; j++) {
        int c = tid + j*64;
        float t = 0.f;
#pragma unroll
        for (int p = 0; p < 32; p++) t += part[(size_t)p*NB*HDIM + (size_t)n*HDIM + c];
        srow[c] = t; s += t*t;
    }
    rs[tid] = s; __syncthreads();
    for (int k = 32; k > 0; k >>= 1) { if (tid < k) rs[tid] += rs[tid+k]; __syncthreads(); }
    float scale = rsqrtf(rs[0] / (float)HDIM + EPSI);
#pragma unroll
    for (int j = 0; j < 3; j++) { int i = tid + j*64; srow[i] = srow[i]*scale*wt[i]; }
    __syncthreads();
    float pos = (float)(ctxl[n] - 1);
    if (tid < 32) {
        int i = tid;
        float x0 = srow[HDIM-RDIM + 2*i], x1 = srow[HDIM-RDIM + 2*i + 1];
        float c, sn; rope_cs(i, pos, c, sn);
        srow[HDIM-RDIM + 2*i]     = x0*c - x1*sn;
        srow[HDIM-RDIM + 2*i + 1] = x0*sn + x1*c;
    }
    __syncthreads();
#pragma unroll
    for (int j = 0; j < 3; j++) { int i = tid + j*64; kv[(size_t)n*HDIM + i] = srow[i]; }
}

/* fused: reduce 6 partials + rope + bf16 split -> g_qhi/g_qlo        */
__global__ void __launch_bounds__(256) k_fuse_q(const float* __restrict__ part,
                                                const int* __restrict__ ctxl,
                                                __nv_bfloat16* __restrict__ qhi,
                                                __nv_bfloat16* __restrict__ qlo)
{
    int n = blockIdx.x, tid = threadIdx.x;
    float pos = (float)(ctxl[n] - 1);
#pragma unroll
    for (int i = 0; i < 12; i++) {
        int p = tid + i*256;
        int e0 = 2*p;
        float v0 = 0.f, v1 = 0.f;
#pragma unroll
        for (int q = 0; q < 6; q++) {
            v0 += part[(size_t)q*NB*QDIM + (size_t)n*QDIM + e0];
            v1 += part[(size_t)q*NB*QDIM + (size_t)n*QDIM + e0 + 1];
        }
        int dd = e0 % HDIM;
        if (dd >= HDIM - RDIM) {
            int ir = (dd - (HDIM - RDIM)) >> 1;
            float c, s; rope_cs(ir, pos, c, s);
            float x0 = v0, x1 = v1;
            v0 = x0*c - x1*s;
            v1 = x0*s + x1*c;
        }
        uint32_t hp, lp;
        split2(v0, v1, hp, lp);
        ((uint32_t*)qhi)[(size_t)n*(QDIM/2) + p] = hp;
        ((uint32_t*)qlo)[(size_t)n*(QDIM/2) + p] = lp;
    }
}

/* ------------------------------------------------------------------ */
/* logits via HMMA with register-prefetch KV pipeline                 */
/* CTA bx (0..7) handles blocks bx, bx+8, ..., bx+56 (strided)        */
/* smem: Qhi 0 | Qlo 12800 | KVhi 25600 | KVlo 51200 | D 76800        */
/* ------------------------------------------------------------------ */
#define LG_SMEM 84992
__global__ void __launch_bounds__(256,2) k_logits_mma(
    const float* __restrict__ kvc, const int* __restrict__ bt,
    const int* __restrict__ ctxl,
    const __nv_bfloat16* __restrict__ qhi, const __nv_bfloat16* __restrict__ qlo,
    const float* __restrict__ kvnew, float* __restrict__ logits)
{
    extern __shared__ char sm[];
    uint32_t smb = smem_u32(sm);
    int n = blockIdx.y;
    int ctx = ctxl[n];
    int bx = blockIdx.x;               /* 0..7 */
    if (bx * BS >= ctx) return;
    int tid = threadIdx.x, wid = tid >> 5, lane = tid & 31;

    {
        const char* gh = (const char*)(qhi + (size_t)n * QDIM);
        const char* gl = (const char*)(qlo + (size_t)n * QDIM);
#pragma unroll
        for (int i = 0; i < 3; i++) {
            int c = tid + i * 256;
            int r = c / 24, k16 = c % 24;
            *(uint4*)(sm + r * 400 + k16 * 16) = *(const uint4*)(gh + r * 384 + k16 * 16);
            *(uint4*)(sm + 12800 + r * 400 + k16 * 16) = *(const uint4*)(gl + r * 384 + k16 * 16);
        }
    }

    int mt = wid & 3;
    int nt = wid >> 2;
    int kvrow = tid >> 2, kvqp = tid & 3;

    float4 kvv[12];
    {   /* prefetch block bx */
        int lg = bx * BS + kvrow;
        const float* src = (lg == ctx - 1) ? (kvnew + (size_t)n * HDIM)
                                           : (kvc + ((size_t)bt[n*MAXB + bx] * BS + kvrow) * HDIM);
#pragma unroll
        for (int j = 0; j < 12; j++) kvv[j] = ((const float4*)src)[kvqp * 12 + j];
    }

    for (int bi = 0; bi < 8; bi++) {
        int b = bx + 8 * bi;
        int base = b * BS;
        if (base >= ctx) break;

#pragma unroll
        for (int j = 0; j < 12; j++)
            cvt_store(sm + 25600, sm + 51200,
                      (uint32_t)(kvrow * 400 + (kvqp * 12 + j) * 8), kvv[j]);
        __syncthreads();                 /* S1 */

        int bnext = bx + 8 * (bi + 1);
        if (bi + 1 < 8 && bnext * BS < ctx) {
            int lg = bnext * BS + kvrow;
            const float* src = (lg == ctx - 1) ? (kvnew + (size_t)n * HDIM)
                                               : (kvc + ((size_t)bt[n*MAXB + bnext] * BS + kvrow) * HDIM);
#pragma unroll
            for (int j = 0; j < 12; j++) kvv[j] = ((const float4*)src)[kvqp * 12 + j];
        }

        float acc[2][4];
#pragma unroll
        for (int i = 0; i < 2; i++)
#pragma unroll
            for (int j = 0; j < 4; j++) acc[i][j] = 0.f;

#pragma unroll
        for (int ks = 0; ks < 12; ks++) {
            uint32_t ah[4], al[4];
            int arow = mt * 16 + (lane & 15);
            uint32_t aoff = (uint32_t)(arow * 400 + ks * 32 + (lane >> 4) * 16);
            ldm_x4(ah, smb + 25600 + aoff);
            ldm_x4(al, smb + 51200 + aoff);
            int brow = nt * 16 + ((lane >> 4) & 1) * 8 + (lane & 7);
            uint32_t boff = (uint32_t)(brow * 400 + ks * 32 + ((lane >> 3) & 1) * 16);
            uint32_t bh[4], bl[4];
            ldm_x4(bh, smb + boff);
            ldm_x4(bl, smb + 12800 + boff);
            mma16816(acc[0], ah, bh);
            mma16816(acc[0], ah, bl);
            mma16816(acc[0], al, bh);
            mma16816(acc[1], ah, bh + 2);
            mma16816(acc[1], ah, bl + 2);
            mma16816(acc[1], al, bh + 2);
        }

        float* D = (float*)(sm + 76800);
#pragma unroll
        for (int n8 = 0; n8 < 2; n8++) {
            int h = nt * 16 + n8 * 8 + (lane & 3) * 2;
            int l = mt * 16 + (lane >> 2);
            D[h * 64 + l]           = acc[n8][0];
            D[(h + 1) * 64 + l]     = acc[n8][1];
            D[h * 64 + l + 8]       = acc[n8][2];
            D[(h + 1) * 64 + l + 8] = acc[n8][3];
        }
        __syncthreads();                 /* S2 */

        int h = tid >> 3, l0 = (tid & 7) * 8;
        float* dst = logits + ((size_t)(n * HEADS + h)) * LMAX + base + l0;
#pragma unroll
        for (int j = 0; j < 8; j++) {
            int l = l0 + j;
            float v = D[h * 64 + l];
            dst[j] = (base + l < ctx) ? v * SCALE_F : NEGF;
        }
    }
}

/* ------------------------------------------------------------------ */
/* top-k radix select (variable length, parallel suffix-sum scan)     */
/* ------------------------------------------------------------------ */
__device__ __forceinline__ unsigned f2ord(float f) {
    unsigned b = __float_as_uint(f);
    return (b & 0x80000000u) ? ~b : (b | 0x80000000u);
}
__device__ __forceinline__ float ord2f(unsigned u) {
    return (u & 0x80000000u) ? __uint_as_float(u ^ 0x80000000u)
                             : __uint_as_float(~u);
}

__global__ void __launch_bounds__(256) k_select(
    const float* __restrict__ logits, const float* __restrict__ sink,
    const int* __restrict__ ctxl,
    float* __restrict__ tau_o, float* __restrict__ m_o, float* __restrict__ iv_o)
{
    __shared__ unsigned keys[LMAX];
    __shared__ unsigned hist[256];
    __shared__ unsigned sfx[256];
    __shared__ unsigned rmax[256];
    __shared__ float    red[256];
    __shared__ unsigned s_prefix;
    __shared__ int      s_k;

    int rowid = blockIdx.x;
    int n = rowid >> 5;
    int h = rowid & 31;
    int tid = threadIdx.x;
    int ctx = ctxl[n];
    int nb = ((ctx + 63) >> 6) << 6;
    const float* src = logits + (size_t)rowid * LMAX;

    unsigned um = 0u;
    for (int idx = tid; idx < nb; idx += 256) {
        unsigned u = f2ord(src[idx]);
        keys[idx] = u;
        um = max(um, u);
    }
    rmax[tid] = um; __syncthreads();
    for (int k = 128; k > 0; k >>= 1) { if (tid < k) rmax[tid] = max(rmax[tid], rmax[tid+k]); __syncthreads(); }

    float maxf = ord2f(rmax[0]);
    float snk  = sink[h];
    float m    = fmaxf(maxf, snk);

    if (nb <= TOPKK) {
        float local = 0.f;
        for (int idx = tid; idx < nb; idx += 256)
            local += __expf(ord2f(keys[idx]) - m);
        red[tid] = local; __syncthreads();
        for (int k = 128; k > 0; k >>= 1) { if (tid < k) red[tid] += red[tid+k]; __syncthreads(); }
        if (tid == 0) {
            float denom = red[0] + __expf(snk - m);
            tau_o[rowid] = -__builtin_huge_valf(); m_o[rowid] = m; iv_o[rowid] = 1.f / denom;
        }
        return;
    }

    if (tid == 0) { s_prefix = 0u; s_k = TOPKK; }
    __syncthreads();

    for (int shift = 24; shift >= 0; shift -= 8) {
        hist[tid] = 0u;
        __syncthreads();
        unsigned pref = s_prefix;
        int kk = s_k;
        unsigned himask = (shift == 24) ? 0u : (0xFFFFFFFFu << (shift + 8));
        for (int idx = tid; idx < nb; idx += 256) {
            unsigned u = keys[idx];
            if ((u & himask) == pref) atomicAdd(&hist[(u >> shift) & 255u], 1u);
        }
        __syncthreads();
        sfx[tid] = hist[tid];
        __syncthreads();
#pragma unroll
        for (int st = 1; st < 256; st <<= 1) {
            unsigned v = (tid + st < 256) ? sfx[tid + st] : 0u;
            __syncthreads();
            sfx[tid] += v;
            __syncthreads();
        }
        unsigned Sb  = sfx[tid];
        unsigned Sn  = (tid == 255) ? 0u : sfx[tid + 1];
        if (Sb >= (unsigned)kk && Sn < (unsigned)kk) {
            s_prefix = pref | ((unsigned)tid << shift);
            s_k = kk - (int)Sn;
        }
        __syncthreads();
    }
    unsigned tu = s_prefix;

    float local = 0.f;
    for (int idx = tid; idx < nb; idx += 256) {
        unsigned u = keys[idx];
        if (u >= tu) local += __expf(ord2f(u) - m);
    }
    red[tid] = local; __syncthreads();
    for (int k = 128; k > 0; k >>= 1) { if (tid < k) red[tid] += red[tid+k]; __syncthreads(); }
    if (tid == 0) {
        float denom = red[0] + __expf(snk - m);
        tau_o[rowid] = ord2f(tu); m_o[rowid] = m; iv_o[rowid] = 1.f / denom;
    }
}

/* ------------------------------------------------------------------ */
/* o accumulation via HMMA with register-prefetch pipeline            */
/* chunk c (0..3) handles blocks c, c+4, ..., c+60 (strided)          */
/* smem: Phi 0 | Plo 4608 | KVhi 9216 | KVlo 34816                    */
/* ------------------------------------------------------------------ */
#define AC_SMEM 60416
__global__ void __launch_bounds__(256,2) k_accum_mma(
    const float* __restrict__ kvc, const int* __restrict__ bt,
    const int* __restrict__ ctxl, const float* __restrict__ kvnew,
    const float* __restrict__ logits, const float* __restrict__ tau_i,
    const float* __restrict__ m_i, const float* __restrict__ iv_i,
    float* __restrict__ opart)
{
    extern __shared__ char sm[];
    uint32_t smb = smem_u32(sm);
    int chunk = blockIdx.x, n = blockIdx.y;
    int ctx = ctxl[n];
    int tid = threadIdx.x, wid = tid >> 5, lane = tid & 31;

    int mt = wid & 1;
    int ng = wid >> 1;
    float acc[6][4];
#pragma unroll
    for (int i = 0; i < 6; i++)
#pragma unroll
        for (int j = 0; j < 4; j++) acc[i][j] = 0.f;

    int ph = tid >> 3, pl0 = (tid & 7) * 8;
    float ptau = tau_i[n*HEADS + ph];
    float pm   = m_i[n*HEADS + ph];
    float piv  = iv_i[n*HEADS + ph];
    int kvrow = tid >> 2, kvqp = tid & 3;

    float4 kvv[12];
    float4 lsv[2];
    {
        int b = chunk, base = b * BS;
        if (base < ctx) {
            int lg = base + kvrow;
            const float* src = (lg == ctx - 1) ? (kvnew + (size_t)n*HDIM)
                                               : (kvc + ((size_t)bt[n*MAXB + b]*BS + kvrow)*HDIM);
#pragma unroll
            for (int j = 0; j < 12; j++) kvv[j] = ((const float4*)src)[kvqp * 12 + j];
            const float4* lf = (const float4*)(logits + ((size_t)(n*HEADS + ph))*LMAX + base + pl0);
            lsv[0] = lf[0]; lsv[1] = lf[1];
        }
    }

    for (int b8 = 0; b8 < 16; b8++) {
        int b = chunk + 4 * b8;
        int base = b * BS;
        if (base >= ctx) break;

        {
            float lg4[8] = {lsv[0].x, lsv[0].y, lsv[0].z, lsv[0].w,
                            lsv[1].x, lsv[1].y, lsv[1].z, lsv[1].w};
#pragma unroll
            for (int j = 0; j < 8; j += 2) {
                float p0 = (lg4[j]   >= ptau) ? (__expf(lg4[j]   - pm) * piv) : 0.f;
                float p1 = (lg4[j+1] >= ptau) ? (__expf(lg4[j+1] - pm) * piv) : 0.f;
                uint32_t hp, lp;
                split2(p0, p1, hp, lp);
                uint32_t off = (uint32_t)(ph * 144 + (pl0 + j) * 2);
                *(uint32_t*)(sm + off)        = hp;
                *(uint32_t*)(sm + 4608 + off) = lp;
            }
        }
#pragma unroll
        for (int j = 0; j < 12; j++)
            cvt_store(sm + 9216, sm + 34816,
                      (uint32_t)(kvrow * 400 + (kvqp * 12 + j) * 8), kvv[j]);
        __syncthreads();                 /* S1 */

        int bn = chunk + 4 * (b8 + 1);
        if (b8 + 1 < 16 && bn * BS < ctx) {
            int lg = bn * BS + kvrow;
            const float* src = (lg == ctx - 1) ? (kvnew + (size_t)n*HDIM)
                                               : (kvc + ((size_t)bt[n*MAXB + bn]*BS + kvrow)*HDIM);
#pragma unroll
            for (int j = 0; j < 12; j++) kvv[j] = ((const float4*)src)[kvqp * 12 + j];
            const float4* lf = (const float4*)(logits + ((size_t)(n*HEADS + ph))*LMAX + bn*BS + pl0);
            lsv[0] = lf[0]; lsv[1] = lf[1];
        }

#pragma unroll
        for (int ks = 0; ks < 4; ks++) {
            uint32_t ah[4], al[4];
            int arow = mt * 16 + (lane & 15);
            uint32_t aoff = (uint32_t)(arow * 144 + ks * 32 + (lane >> 4) * 16);
            ldm_x4(ah, smb + aoff);
            ldm_x4(al, smb + 4608 + aoff);
            int l_in = ks * 16 + ((lane >> 3) & 1) * 8 + (lane & 7);
#pragma unroll
            for (int t = 0; t < 3; t++) {
                uint32_t dByte = (uint32_t)((ng * 48 + t * 16) * 2 + ((lane >> 4) & 1) * 16);
                uint32_t boff = (uint32_t)(l_in * 400) + dByte;
                uint32_t bh[4], bl[4];
                ldm_x4t(bh, smb + 9216 + boff);
                ldm_x4t(bl, smb + 34816 + boff);
                mma16816(acc[2*t],   ah, bh);
                mma16816(acc[2*t],   ah, bl);
                mma16816(acc[2*t],   al, bh);
                mma16816(acc[2*t+1], ah, bh + 2);
                mma16816(acc[2*t+1], ah, bl + 2);
                mma16816(acc[2*t+1], al, bh + 2);
            }
        }
        __syncthreads();                 /* S2 */
    }

    float* dst = opart + ((size_t)(chunk * NB + n)) * HEADS * HDIM;
#pragma unroll
    for (int t6 = 0; t6 < 6; t6++) {
        int d = ng * 48 + t6 * 8 + (lane & 3) * 2;
        int h = mt * 16 + (lane >> 2);
        dst[(size_t)h * HDIM + d]           = acc[t6][0];
        dst[(size_t)h * HDIM + d + 1]       = acc[t6][1];
        dst[(size_t)(h + 8) * HDIM + d]     = acc[t6][2];
        dst[(size_t)(h + 8) * HDIM + d + 1] = acc[t6][3];
    }
}

/* reduce 4 o-partials -> bf16 hi/lo pairs */
__global__ void k_reduce_o(const float* __restrict__ opart,
                           __nv_bfloat16* __restrict__ ohi,
                           __nv_bfloat16* __restrict__ olo)
{
    int p = blockIdx.x*256 + threadIdx.x;
    int e0 = 2 * p;
    float v0 = 0.f, v1 = 0.f;
#pragma unroll
    for (int c = 0; c < 4; c++) {
        v0 += opart[(size_t)c*NB*QDIM + e0];
        v1 += opart[(size_t)c*NB*QDIM + e0 + 1];
    }
    uint32_t hp, lp;
    split2(v0, v1, hp, lp);
    ((uint32_t*)ohi)[p] = hp;
    ((uint32_t*)olo)[p] = lp;
}

/* ------------------------------------------------------------------ */
/* host launcher (stream fork/join during graph capture)              */
/* ------------------------------------------------------------------ */
extern "C" void kernel_launch(void* const* d_in, const int* in_sizes, int n_in,
                              void* d_out, int out_size)
{
    const float* x    = (const float*)d_in[0];
    const float* kvc  = (const float*)d_in[1];
    const int*   bt   = (const int*)  d_in[2];
    const int*   ctxl = (const int*)  d_in[3];
    const float* wqa  = (const float*)d_in[5];
    const float* qnw  = (const float*)d_in[6];
    const float* wqb  = (const float*)d_in[7];
    const float* wkv  = (const float*)d_in[8];
    const float* kvnw = (const float*)d_in[9];
    const float* woa  = (const float*)d_in[10];
    const float* wob  = (const float*)d_in[11];
    const float* sink = (const float*)d_in[12];
    float* out = (float*)d_out;

    float *kv, *lg, *tau, *mr, *iv, *op, *part;
    __nv_bfloat16 *xhi, *xlo, *qahi, *qalo, *qhi, *qlo, *oohi, *oolo, *lathi, *latlo;
    cudaGetSymbolAddress((void**)&xhi,  g_xhi);
    cudaGetSymbolAddress((void**)&xlo,  g_xlo);
    cudaGetSymbolAddress((void**)&qahi, g_qahi);
    cudaGetSymbolAddress((void**)&qalo, g_qalo);
    cudaGetSymbolAddress((void**)&kv,   g_kv);
    cudaGetSymbolAddress((void**)&qhi,  g_qhi);
    cudaGetSymbolAddress((void**)&qlo,  g_qlo);
    cudaGetSymbolAddress((void**)&lg,   g_logits);
    cudaGetSymbolAddress((void**)&tau,  g_tau);
    cudaGetSymbolAddress((void**)&mr,   g_mrow);
    cudaGetSymbolAddress((void**)&iv,   g_invden);
    cudaGetSymbolAddress((void**)&op,   g_opart);
    cudaGetSymbolAddress((void**)&oohi, g_oohi);
    cudaGetSymbolAddress((void**)&oolo, g_oolo);
    cudaGetSymbolAddress((void**)&lathi,g_lathi);
    cudaGetSymbolAddress((void**)&latlo,g_latlo);
    cudaGetSymbolAddress((void**)&part, g_part);

    static cudaStream_t s1 = 0;
    static cudaEvent_t  e0 = 0, e1 = 0;
    if (!s1) {
        cudaStreamCreateWithFlags(&s1, cudaStreamNonBlocking);
        cudaEventCreateWithFlags(&e0, cudaEventDisableTiming);
        cudaEventCreateWithFlags(&e1, cudaEventDisableTiming);
        cudaFuncSetAttribute(k_gemm_mma,   cudaFuncAttributeMaxDynamicSharedMemorySize, MM_SMEM);
        cudaFuncSetAttribute(k_logits_mma, cudaFuncAttributeMaxDynamicSharedMemorySize, LG_SMEM);
        cudaFuncSetAttribute(k_accum_mma,  cudaFuncAttributeMaxDynamicSharedMemorySize, AC_SMEM);
        cudaFuncSetAttribute(k_gemm_mma,   cudaFuncAttributePreferredSharedMemoryCarveout, 50);
        cudaFuncSetAttribute(k_logits_mma, cudaFuncAttributePreferredSharedMemoryCarveout, 76);
        cudaFuncSetAttribute(k_accum_mma,  cudaFuncAttributePreferredSharedMemoryCarveout, 55);
    }

    /* ---- x -> bf16 hi/lo ---- */
    k_x2bf<<<NB*DIMX/512, 256>>>(x, xhi, xlo);
    cudaEventRecord(e0, 0);
    cudaStreamWaitEvent(s1, e0, 0);

    /* ---- branch A (stream 0): wq_a -> rms -> wq_b -> rope/split ---- */
    k_gemm_mma<<<dim3(12, 16, 1), 256, MM_SMEM>>>(
        xhi, xlo, DIMX, 0, wqa, DIMX, 0,
        part + PART_QA_OFF, QLRK, 0, (long long)NB*QLRK, 256, QLRK);
    k_fuse_qa<<<NB, 256>>>(part + PART_QA_OFF, qnw, qahi, qalo);
    k_gemm_mma<<<dim3(48, 6, 1), 256, MM_SMEM>>>(
        qahi, qalo, QLRK, 0, wqb, QLRK, 0,
        part + PART_QB_OFF, QDIM, 0, (long long)NB*QDIM, 256, QDIM);
    k_fuse_q<<<NB, 256>>>(part + PART_QB_OFF, ctxl, qhi, qlo);

    /* ---- branch B (stream s1): wkv -> rms+rope ---- */
    k_gemm_mma<<<dim3(2, 32, 1), 256, MM_SMEM, s1>>>(
        xhi, xlo, DIMX, 0, wkv, DIMX, 0,
        part + PART_KV_OFF, HDIM, 0, (long long)NB*HDIM, 128, HDIM);
    k_fuse_kv<<<NB, 64, 0, s1>>>(part + PART_KV_OFF, kvnw, ctxl, kv);
    cudaEventRecord(e1, s1);
    cudaStreamWaitEvent(0, e1, 0);

    /* ---- attention ---- */
    k_logits_mma<<<dim3(8, NB), 256, LG_SMEM>>>(kvc, bt, ctxl, qhi, qlo, kv, lg);
    k_select<<<NB*HEADS, 256>>>(lg, sink, ctxl, tau, mr, iv);
    k_accum_mma<<<dim3(4, NB), 256, AC_SMEM>>>(kvc, bt, ctxl, kv, lg, tau, mr, iv, op);
    k_reduce_o<<<NB*QDIM/512, 256>>>(op, oohi, oolo);

    /* ---- lat = grouped wo_a : split 6 (192 CTAs = 1 wave) ---- */
    k_gemm_mma<<<dim3(4, 6, GRP), 256, MM_SMEM>>>(
        oohi, oolo, QDIM, 768, woa, 768, (long long)OLRK*768,
        part, GRP*OLRK, OLRK, (long long)NB*GRP*OLRK, 128, OLRK);
    k_reduce_bf<<<(NB*GRP*OLRK/2+255)/256, 256>>>(part, lathi, latlo,
                                                  NB*GRP*OLRK/2, NB*GRP*OLRK, 6);

    /* ---- out = lat @ wo_b^T : split 8 (256 CTAs = 1 wave) ---- */
    k_gemm_mma<<<dim3(32, 8, 1), 256, MM_SMEM>>>(
        lathi, latlo, GRP*OLRK, 0, wob, DIMX, 0,
        part, DIMX, 0, (long long)NB*DIMX, 512, DIMX);
    k_reduce<<<(NB*DIMX+255)/256, 256>>>(part, out, NB*DIMX, 8);
}

// round 16
// speedup vs baseline: 1.0890x; 1.0890x over previous
#include <cuda_runtime.h>
#include <cuda_bf16.h>
#include <math.h>
#include <stdint.h>

#define NB    64
#define DIMX  4096
#define HEADS 32
#define HDIM  192
#define RDIM  64
#define QLRK  1536
#define OLRK  512
#define GRP   8
#define BS    64
#define MAXB  64
#define LMAX  4096
#define TOPKK 1024
#define EPSI  1e-6f
#define NEGF  -1e30f
#define QDIM  (HEADS*HDIM)   /* 6144 */
#define SCALE_F 0.07216878364870323f  /* 192^-0.5 */

/* disjoint split-K partial regions (floats) */
#define PART_QA_OFF 0                         /* 16*98304  = 1572864 */
#define PART_KV_OFF 1572864                   /* 32*12288  = 393216  */
#define PART_QB_OFF 1966080                   /* 6*393216  = 2359296 */
#define PART_TOTAL  4325376                   /* 16.5 MB */

/* ------------------------------------------------------------------ */
/* scratch                                                            */
/* ------------------------------------------------------------------ */
__device__ __nv_bfloat16 g_xhi[NB*DIMX];
__device__ __nv_bfloat16 g_xlo[NB*DIMX];
__device__ __nv_bfloat16 g_qahi[NB*QLRK];
__device__ __nv_bfloat16 g_qalo[NB*QLRK];
__device__ float g_kv[NB*HDIM];
__device__ __nv_bfloat16 g_qhi[NB*QDIM];
__device__ __nv_bfloat16 g_qlo[NB*QDIM];
__device__ float g_logits[(size_t)NB*HEADS*LMAX];       /* 32 MB */
__device__ float g_tau[NB*HEADS];
__device__ float g_mrow[NB*HEADS];
__device__ float g_invden[NB*HEADS];
__device__ float g_opart[(size_t)8*NB*HEADS*HDIM];      /* 12.6 MB */
__device__ __nv_bfloat16 g_oohi[NB*QDIM];
__device__ __nv_bfloat16 g_oolo[NB*QDIM];
__device__ __nv_bfloat16 g_lathi[NB*GRP*OLRK];
__device__ __nv_bfloat16 g_latlo[NB*GRP*OLRK];
__device__ float g_part[PART_TOTAL];

/* ------------------------------------------------------------------ */
/* helpers                                                            */
/* ------------------------------------------------------------------ */
__device__ __forceinline__ uint32_t smem_u32(const void* p){
    uint32_t a;
    asm("{ .reg .u64 t; cvta.to.shared.u64 t, %1; cvt.u32.u64 %0, t; }"
        : "=r"(a) : "l"(p));
    return a;
}
__device__ __forceinline__ uint32_t sw128(uint32_t b){ return b ^ ((b >> 3) & 0x70); }

/* fast exact split: hi = truncate-to-bf16 (bit prefix), lo = rn(v-hi). */
__device__ __forceinline__ void split2(float x, float y, uint32_t& hp, uint32_t& lp){
    uint32_t bx = __float_as_uint(x), by = __float_as_uint(y);
    uint32_t h;
    asm("prmt.b32 %0, %1, %2, 0x7632;" : "=r"(h) : "r"(bx), "r"(by));
    float fx = __uint_as_float(h << 16);
    float fy = __uint_as_float(h & 0xFFFF0000u);
    float lx = x - fx, ly = y - fy;
    uint32_t l;
    asm("cvt.rn.bf16x2.f32 %0, %1, %2;" : "=r"(l) : "f"(ly), "f"(lx));
    hp = h; lp = l;
}
__device__ __forceinline__ void mma16816(float* c, const uint32_t* a, const uint32_t* b){
    asm volatile("mma.sync.aligned.m16n8k16.row.col.f32.bf16.bf16.f32 "
        "{%0,%1,%2,%3}, {%4,%5,%6,%7}, {%8,%9}, {%0,%1,%2,%3};"
        : "+f"(c[0]), "+f"(c[1]), "+f"(c[2]), "+f"(c[3])
        : "r"(a[0]), "r"(a[1]), "r"(a[2]), "r"(a[3]), "r"(b[0]), "r"(b[1]));
}
__device__ __forceinline__ void ldm_x4(uint32_t* r, uint32_t addr){
    asm volatile("ldmatrix.sync.aligned.m8n8.x4.shared.b16 {%0,%1,%2,%3}, [%4];"
        : "=r"(r[0]), "=r"(r[1]), "=r"(r[2]), "=r"(r[3]) : "r"(addr));
}
__device__ __forceinline__ void ldm_x4t(uint32_t* r, uint32_t addr){
    asm volatile("ldmatrix.sync.aligned.m8n8.x4.trans.shared.b16 {%0,%1,%2,%3}, [%4];"
        : "=r"(r[0]), "=r"(r[1]), "=r"(r[2]), "=r"(r[3]) : "r"(addr));
}
__device__ __forceinline__ void cvt_store(char* hiB, char* loB, uint32_t off, float4 v){
    uint2 hh, ll;
    split2(v.x, v.y, hh.x, ll.x);
    split2(v.z, v.w, hh.y, ll.y);
    *(uint2*)(hiB + off) = hh;
    *(uint2*)(loB + off) = ll;
}

/* ------------------------------------------------------------------ */
/* HMMA GEMM (round-12 best config: single stage, warp tile 32x32)    */
/* ------------------------------------------------------------------ */
#define MM_SMEM 49152
__global__ void __launch_bounds__(256,2) k_gemm_mma(
    const __nv_bfloat16* __restrict__ Xhi, const __nv_bfloat16* __restrict__ Xlo,
    int ldx, long long xGrp,
    const float* __restrict__ W, int ldw, long long wGrp,
    float* __restrict__ C, int ldc, long long cGrp, long long cSplit,
    int Kloc, int Nw)
{
    extern __shared__ char sm[];
    char* sXhi = sm;
    char* sXlo = sm + 8192;
    char* sWhi = sm + 16384;
    char* sWlo = sm + 32768;
    uint32_t smb = smem_u32(sm);

    int tid = threadIdx.x, wid = tid >> 5, lane = tid & 31;
    int n0 = blockIdx.x * 128;
    int s  = blockIdx.y;
    int g  = blockIdx.z;
    Xhi += (size_t)g * xGrp + (size_t)s * Kloc;
    Xlo += (size_t)g * xGrp + (size_t)s * Kloc;
    W   += (size_t)g * wGrp + (size_t)s * Kloc;
    C   += (size_t)g * cGrp + (size_t)s * cSplit;

    int wm = (wid & 1) * 32;
    int wn = (wid >> 1) * 32;

    float acc[8][4];
#pragma unroll
    for (int i = 0; i < 8; i++)
#pragma unroll
        for (int j = 0; j < 4; j++) acc[i][j] = 0.f;

    int xr0 = tid >> 3, xr1 = (tid + 256) >> 3;
    int xc16 = tid & 7;
    int wrow = tid >> 1;
    int wc   = tid & 1;
    int wrg  = n0 + wrow; if (wrg >= Nw) wrg = Nw - 1;

    const int NC = Kloc / 64;
    uint4 xh[2], xl[2];
    float4 wv[8];
    xh[0] = *(const uint4*)(Xhi + (size_t)xr0 * ldx + xc16 * 8);
    xh[1] = *(const uint4*)(Xhi + (size_t)xr1 * ldx + xc16 * 8);
    xl[0] = *(const uint4*)(Xlo + (size_t)xr0 * ldx + xc16 * 8);
    xl[1] = *(const uint4*)(Xlo + (size_t)xr1 * ldx + xc16 * 8);
#pragma unroll
    for (int j = 0; j < 8; j++)
        wv[j] = *(const float4*)(W + (size_t)wrg * ldw + (wc + 2*j) * 4);

    for (int ch = 0; ch < NC; ch++) {
        if (ch) __syncthreads();
        {
            uint32_t o0 = sw128((uint32_t)(xr0 * 128 + xc16 * 16));
            uint32_t o1 = sw128((uint32_t)(xr1 * 128 + xc16 * 16));
            *(uint4*)(sXhi + o0) = xh[0];
            *(uint4*)(sXhi + o1) = xh[1];
            *(uint4*)(sXlo + o0) = xl[0];
            *(uint4*)(sXlo + o1) = xl[1];
        }
#pragma unroll
        for (int j = 0; j < 8; j++) {
            uint32_t off = sw128((uint32_t)(wrow * 128 + (wc + 2*j) * 8));
            cvt_store(sWhi, sWlo, off, wv[j]);
        }
        __syncthreads();
        if (ch + 1 < NC) {
            int kb = (ch + 1) * 64;
            xh[0] = *(const uint4*)(Xhi + (size_t)xr0 * ldx + kb + xc16 * 8);
            xh[1] = *(const uint4*)(Xhi + (size_t)xr1 * ldx + kb + xc16 * 8);
            xl[0] = *(const uint4*)(Xlo + (size_t)xr0 * ldx + kb + xc16 * 8);
            xl[1] = *(const uint4*)(Xlo + (size_t)xr1 * ldx + kb + xc16 * 8);
#pragma unroll
            for (int j = 0; j < 8; j++)
                wv[j] = *(const float4*)(W + (size_t)wrg * ldw + kb + (wc + 2*j) * 4);
        }
#pragma unroll
        for (int ks = 0; ks < 4; ks++) {
            uint32_t ah[2][4], al[2][4];
#pragma unroll
            for (int mtq = 0; mtq < 2; mtq++) {
                int arow = wm + mtq * 16 + (lane & 15);
                uint32_t aoff = sw128((uint32_t)(arow * 128 + (ks*2 + (lane >> 4)) * 16));
                ldm_x4(ah[mtq], smb + aoff);
                ldm_x4(al[mtq], smb + 8192 + aoff);
            }
#pragma unroll
            for (int t = 0; t < 2; t++) {
                int brow = wn + 16*t + ((lane >> 4) & 1) * 8 + (lane & 7);
                uint32_t boff = sw128((uint32_t)(brow * 128 + (ks*2 + ((lane >> 3) & 1)) * 16));
                uint32_t bh[4], bl[4];
                ldm_x4(bh, smb + 16384 + boff);
                ldm_x4(bl, smb + 32768 + boff);
#pragma unroll
                for (int mtq = 0; mtq < 2; mtq++) {
                    float* a0 = acc[mtq*4 + t*2];
                    float* a1 = acc[mtq*4 + t*2 + 1];
                    mma16816(a0, ah[mtq], bh);
                    mma16816(a0, ah[mtq], bl);
                    mma16816(a0, al[mtq], bh);
                    mma16816(a1, ah[mtq], bh + 2);
                    mma16816(a1, ah[mtq], bl + 2);
                    mma16816(a1, al[mtq], bh + 2);
                }
            }
        }
    }

#pragma unroll
    for (int mtq = 0; mtq < 2; mtq++) {
        int mr = wm + mtq * 16 + (lane >> 2);
#pragma unroll
        for (int sub = 0; sub < 4; sub++) {
            int nc = n0 + wn + sub * 8 + (lane & 3) * 2;
            float* a = acc[mtq*4 + sub];
            if (nc < Nw) {
                C[(size_t)mr * ldc + nc]       = a[0];
                C[(size_t)(mr + 8) * ldc + nc] = a[2];
            }
            if (nc + 1 < Nw) {
                C[(size_t)mr * ldc + nc + 1]       = a[1];
                C[(size_t)(mr + 8) * ldc + nc + 1] = a[3];
            }
        }
    }
}

/* generic split-K reduce -> fp32 */
__global__ void k_reduce(const float* __restrict__ part, float* __restrict__ out,
                         int E, int S)
{
    int i = blockIdx.x * 256 + threadIdx.x;
    if (i >= E) return;
    float s = 0.f;
    for (int p = 0; p < S; p++) s += part[(size_t)p * E + i];
    out[i] = s;
}

/* split-K reduce -> bf16 hi/lo pairs */
__global__ void k_reduce_bf(const float* __restrict__ part,
                            __nv_bfloat16* __restrict__ ohi,
                            __nv_bfloat16* __restrict__ olo,
                            int Epairs, int E, int S)
{
    int p = blockIdx.x * 256 + threadIdx.x;
    if (p >= Epairs) return;
    int e0 = 2 * p;
    float v0 = 0.f, v1 = 0.f;
    for (int q = 0; q < S; q++) {
        v0 += part[(size_t)q * E + e0];
        v1 += part[(size_t)q * E + e0 + 1];
    }
    uint32_t hp, lp;
    split2(v0, v1, hp, lp);
    ((uint32_t*)ohi)[p] = hp;
    ((uint32_t*)olo)[p] = lp;
}

/* x fp32 -> bf16 hi/lo */
__global__ void __launch_bounds__(256) k_x2bf(const float* __restrict__ x,
                                              __nv_bfloat16* __restrict__ xhi,
                                              __nv_bfloat16* __restrict__ xlo)
{
    int p = blockIdx.x * 256 + threadIdx.x;
    float2 v = ((const float2*)x)[p];
    uint32_t hp, lp;
    split2(v.x, v.y, hp, lp);
    ((uint32_t*)xhi)[p] = hp;
    ((uint32_t*)xlo)[p] = lp;
}

/* ------------------------------------------------------------------ */
/* fused: reduce 16 partials + RMS(q_norm) -> bf16 hi/lo              */
/* ------------------------------------------------------------------ */
__global__ void __launch_bounds__(256) k_fuse_qa(const float* __restrict__ part,
                                                 const float* __restrict__ wt,
                                                 __nv_bfloat16* __restrict__ qahi,
                                                 __nv_bfloat16* __restrict__ qalo)
{
    __shared__ float red[256];
    int n = blockIdx.x, tid = threadIdx.x;
    float v0[3], v1[3]; float s = 0.f;
#pragma unroll
    for (int i = 0; i < 3; i++) {
        int e0 = 2 * (tid + i*256);
        float a = 0.f, b = 0.f;
#pragma unroll
        for (int p = 0; p < 16; p++) {
            a += part[(size_t)p*NB*QLRK + (size_t)n*QLRK + e0];
            b += part[(size_t)p*NB*QLRK + (size_t)n*QLRK + e0 + 1];
        }
        v0[i] = a; v1[i] = b; s += a*a + b*b;
    }
    red[tid] = s; __syncthreads();
    for (int k = 128; k > 0; k >>= 1) { if (tid < k) red[tid] += red[tid+k]; __syncthreads(); }
    float scale = rsqrtf(red[0] / (float)QLRK + EPSI);
#pragma unroll
    for (int i = 0; i < 3; i++) {
        int p = tid + i*256;
        int e0 = 2 * p;
        float f0 = v0[i] * scale * wt[e0];
        float f1 = v1[i] * scale * wt[e0 + 1];
        uint32_t hp, lp;
        split2(f0, f1, hp, lp);
        ((uint32_t*)qahi)[(size_t)n*(QLRK/2) + p] = hp;
        ((uint32_t*)qalo)[(size_t)n*(QLRK/2) + p] = lp;
    }
}

__device__ __forceinline__ void rope_cs(int i, float pos, float& c, float& s)
{
    float inv = (float)exp(-(double)i * 0.28782313662425574); /* ln(1e4)/32 */
    float ang = pos * inv;
    double ad = (double)ang;
    c = (float)cos(ad); s = (float)sin(ad);
}

/* fused: reduce 32 partials + RMS + rope -> g_kv (fp32)              */
__global__ void k_fuse_kv(const float* __restrict__ part,
                          const float* __restrict__ wt,
                          const int* __restrict__ ctxl,
                          float* __restrict__ kv)
{
    __shared__ float srow[HDIM];
    __shared__ float rs[64];
    int n = blockIdx.x, tid = threadIdx.x;
    float s = 0.f;
#pragma unroll
    for (int j = 0; j < 3; j++) {
        int c = tid + j*64;
        float t = 0.f;
#pragma unroll
        for (int p = 0; p < 32; p++) t += part[(size_t)p*NB*HDIM + (size_t)n*HDIM + c];
        srow[c] = t; s += t*t;
    }
    rs[tid] = s; __syncthreads();
    for (int k = 32; k > 0; k >>= 1) { if (tid < k) rs[tid] += rs[tid+k]; __syncthreads(); }
    float scale = rsqrtf(rs[0] / (float)HDIM + EPSI);
#pragma unroll
    for (int j = 0; j < 3; j++) { int i = tid + j*64; srow[i] = srow[i]*scale*wt[i]; }
    __syncthreads();
    float pos = (float)(ctxl[n] - 1);
    if (tid < 32) {
        int i = tid;
        float x0 = srow[HDIM-RDIM + 2*i], x1 = srow[HDIM-RDIM + 2*i + 1];
        float c, sn; rope_cs(i, pos, c, sn);
        srow[HDIM-RDIM + 2*i]     = x0*c - x1*sn;
        srow[HDIM-RDIM + 2*i + 1] = x0*sn + x1*c;
    }
    __syncthreads();
#pragma unroll
    for (int j = 0; j < 3; j++) { int i = tid + j*64; kv[(size_t)n*HDIM + i] = srow[i]; }
}

/* fused: reduce 6 partials + rope + bf16 split -> g_qhi/g_qlo        */
__global__ void __launch_bounds__(256) k_fuse_q(const float* __restrict__ part,
                                                const int* __restrict__ ctxl,
                                                __nv_bfloat16* __restrict__ qhi,
                                                __nv_bfloat16* __restrict__ qlo)
{
    int n = blockIdx.x, tid = threadIdx.x;
    float pos = (float)(ctxl[n] - 1);
#pragma unroll
    for (int i = 0; i < 12; i++) {
        int p = tid + i*256;
        int e0 = 2*p;
        float v0 = 0.f, v1 = 0.f;
#pragma unroll
        for (int q = 0; q < 6; q++) {
            v0 += part[(size_t)q*NB*QDIM + (size_t)n*QDIM + e0];
            v1 += part[(size_t)q*NB*QDIM + (size_t)n*QDIM + e0 + 1];
        }
        int dd = e0 % HDIM;
        if (dd >= HDIM - RDIM) {
            int ir = (dd - (HDIM - RDIM)) >> 1;
            float c, s; rope_cs(ir, pos, c, s);
            float x0 = v0, x1 = v1;
            v0 = x0*c - x1*s;
            v1 = x0*s + x1*c;
        }
        uint32_t hp, lp;
        split2(v0, v1, hp, lp);
        ((uint32_t*)qhi)[(size_t)n*(QDIM/2) + p] = hp;
        ((uint32_t*)qlo)[(size_t)n*(QDIM/2) + p] = lp;
    }
}

/* ------------------------------------------------------------------ */
/* logits via HMMA with register-prefetch KV pipeline                 */
/* CTA bx (0..15) handles blocks bx, bx+16, bx+32, bx+48 (strided)    */
/* smem: Qhi 0 | Qlo 12800 | KVhi 25600 | KVlo 51200 | D 76800        */
/* ------------------------------------------------------------------ */
#define LG_SMEM 84992
__global__ void __launch_bounds__(256,2) k_logits_mma(
    const float* __restrict__ kvc, const int* __restrict__ bt,
    const int* __restrict__ ctxl,
    const __nv_bfloat16* __restrict__ qhi, const __nv_bfloat16* __restrict__ qlo,
    const float* __restrict__ kvnew, float* __restrict__ logits)
{
    extern __shared__ char sm[];
    uint32_t smb = smem_u32(sm);
    int n = blockIdx.y;
    int ctx = ctxl[n];
    int bx = blockIdx.x;               /* 0..15 */
    if (bx * BS >= ctx) return;
    int tid = threadIdx.x, wid = tid >> 5, lane = tid & 31;

    {
        const char* gh = (const char*)(qhi + (size_t)n * QDIM);
        const char* gl = (const char*)(qlo + (size_t)n * QDIM);
#pragma unroll
        for (int i = 0; i < 3; i++) {
            int c = tid + i * 256;
            int r = c / 24, k16 = c % 24;
            *(uint4*)(sm + r * 400 + k16 * 16) = *(const uint4*)(gh + r * 384 + k16 * 16);
            *(uint4*)(sm + 12800 + r * 400 + k16 * 16) = *(const uint4*)(gl + r * 384 + k16 * 16);
        }
    }

    int mt = wid & 3;
    int nt = wid >> 2;
    int kvrow = tid >> 2, kvqp = tid & 3;

    float4 kvv[12];
    {   /* prefetch block bx */
        int lg = bx * BS + kvrow;
        const float* src = (lg == ctx - 1) ? (kvnew + (size_t)n * HDIM)
                                           : (kvc + ((size_t)bt[n*MAXB + bx] * BS + kvrow) * HDIM);
#pragma unroll
        for (int j = 0; j < 12; j++) kvv[j] = ((const float4*)src)[kvqp * 12 + j];
    }

    for (int bi = 0; bi < 4; bi++) {
        int b = bx + 16 * bi;
        int base = b * BS;
        if (base >= ctx) break;

#pragma unroll
        for (int j = 0; j < 12; j++)
            cvt_store(sm + 25600, sm + 51200,
                      (uint32_t)(kvrow * 400 + (kvqp * 12 + j) * 8), kvv[j]);
        __syncthreads();                 /* S1 */

        int bnext = bx + 16 * (bi + 1);
        if (bi + 1 < 4 && bnext * BS < ctx) {
            int lg = bnext * BS + kvrow;
            const float* src = (lg == ctx - 1) ? (kvnew + (size_t)n * HDIM)
                                               : (kvc + ((size_t)bt[n*MAXB + bnext] * BS + kvrow) * HDIM);
#pragma unroll
            for (int j = 0; j < 12; j++) kvv[j] = ((const float4*)src)[kvqp * 12 + j];
        }

        float acc[2][4];
#pragma unroll
        for (int i = 0; i < 2; i++)
#pragma unroll
            for (int j = 0; j < 4; j++) acc[i][j] = 0.f;

#pragma unroll
        for (int ks = 0; ks < 12; ks++) {
            uint32_t ah[4], al[4];
            int arow = mt * 16 + (lane & 15);
            uint32_t aoff = (uint32_t)(arow * 400 + ks * 32 + (lane >> 4) * 16);
            ldm_x4(ah, smb + 25600 + aoff);
            ldm_x4(al, smb + 51200 + aoff);
            int brow = nt * 16 + ((lane >> 4) & 1) * 8 + (lane & 7);
            uint32_t boff = (uint32_t)(brow * 400 + ks * 32 + ((lane >> 3) & 1) * 16);
            uint32_t bh[4], bl[4];
            ldm_x4(bh, smb + boff);
            ldm_x4(bl, smb + 12800 + boff);
            mma16816(acc[0], ah, bh);
            mma16816(acc[0], ah, bl);
            mma16816(acc[0], al, bh);
            mma16816(acc[1], ah, bh + 2);
            mma16816(acc[1], ah, bl + 2);
            mma16816(acc[1], al, bh + 2);
        }

        float* D = (float*)(sm + 76800);
#pragma unroll
        for (int n8 = 0; n8 < 2; n8++) {
            int h = nt * 16 + n8 * 8 + (lane & 3) * 2;
            int l = mt * 16 + (lane >> 2);
            D[h * 64 + l]           = acc[n8][0];
            D[(h + 1) * 64 + l]     = acc[n8][1];
            D[h * 64 + l + 8]       = acc[n8][2];
            D[(h + 1) * 64 + l + 8] = acc[n8][3];
        }
        __syncthreads();                 /* S2 */

        int h = tid >> 3, l0 = (tid & 7) * 8;
        float* dst = logits + ((size_t)(n * HEADS + h)) * LMAX + base + l0;
#pragma unroll
        for (int j = 0; j < 8; j++) {
            int l = l0 + j;
            float v = D[h * 64 + l];
            dst[j] = (base + l < ctx) ? v * SCALE_F : NEGF;
        }
    }
}

/* ------------------------------------------------------------------ */
/* top-k radix select (variable length, warp-shuffle suffix scan)     */
/* ------------------------------------------------------------------ */
__device__ __forceinline__ unsigned f2ord(float f) {
    unsigned b = __float_as_uint(f);
    return (b & 0x80000000u) ? ~b : (b | 0x80000000u);
}
__device__ __forceinline__ float ord2f(unsigned u) {
    return (u & 0x80000000u) ? __uint_as_float(u ^ 0x80000000u)
                             : __uint_as_float(~u);
}

__global__ void __launch_bounds__(256) k_select(
    const float* __restrict__ logits, const float* __restrict__ sink,
    const int* __restrict__ ctxl,
    float* __restrict__ tau_o, float* __restrict__ m_o, float* __restrict__ iv_o)
{
    __shared__ unsigned keys[LMAX];
    __shared__ unsigned hist[256];
    __shared__ unsigned wsum[8];
    __shared__ unsigned rmax[256];
    __shared__ float    red[256];
    __shared__ unsigned s_prefix;
    __shared__ int      s_k;

    int rowid = blockIdx.x;
    int n = rowid >> 5;
    int h = rowid & 31;
    int tid = threadIdx.x;
    int w = tid >> 5, l = tid & 31;
    int ctx = ctxl[n];
    int nb = ((ctx + 63) >> 6) << 6;
    const float* src = logits + (size_t)rowid * LMAX;

    unsigned um = 0u;
    for (int idx = tid; idx < nb; idx += 256) {
        unsigned u = f2ord(src[idx]);
        keys[idx] = u;
        um = max(um, u);
    }
    rmax[tid] = um; __syncthreads();
    for (int k = 128; k > 0; k >>= 1) { if (tid < k) rmax[tid] = max(rmax[tid], rmax[tid+k]); __syncthreads(); }

    float maxf = ord2f(rmax[0]);
    float snk  = sink[h];
    float m    = fmaxf(maxf, snk);

    if (nb <= TOPKK) {
        float local = 0.f;
        for (int idx = tid; idx < nb; idx += 256)
            local += __expf(ord2f(keys[idx]) - m);
        red[tid] = local; __syncthreads();
        for (int k = 128; k > 0; k >>= 1) { if (tid < k) red[tid] += red[tid+k]; __syncthreads(); }
        if (tid == 0) {
            float denom = red[0] + __expf(snk - m);
            tau_o[rowid] = -__builtin_huge_valf(); m_o[rowid] = m; iv_o[rowid] = 1.f / denom;
        }
        return;
    }

    if (tid == 0) { s_prefix = 0u; s_k = TOPKK; }
    __syncthreads();

    for (int shift = 24; shift >= 0; shift -= 8) {
        hist[tid] = 0u;
        __syncthreads();
        unsigned pref = s_prefix;
        int kk = s_k;
        unsigned himask = (shift == 24) ? 0u : (0xFFFFFFFFu << (shift + 8));
        for (int idx = tid; idx < nb; idx += 256) {
            unsigned u = keys[idx];
            if ((u & himask) == pref) atomicAdd(&hist[(u >> shift) & 255u], 1u);
        }
        __syncthreads();
        /* warp-shuffle inclusive suffix scan over 256 bins */
        unsigned hv = hist[tid];
        unsigned v  = hv;
#pragma unroll
        for (int st = 1; st < 32; st <<= 1) {
            unsigned t = __shfl_down_sync(0xFFFFFFFFu, v, st);
            if (l + st < 32) v += t;
        }
        if (l == 0) wsum[w] = v;     /* warp segment total (from lane0's suffix) */
        __syncthreads();
        unsigned add = 0u;
#pragma unroll
        for (int q = 0; q < 8; q++)
            if (q > w) add += wsum[q];
        unsigned Sb = v + add;        /* inclusive suffix sum at tid */
        unsigned Sn = Sb - hv;        /* suffix sum at tid+1 */
        if (Sb >= (unsigned)kk && Sn < (unsigned)kk) {
            s_prefix = pref | ((unsigned)tid << shift);
            s_k = kk - (int)Sn;
        }
        __syncthreads();
    }
    unsigned tu = s_prefix;

    float local = 0.f;
    for (int idx = tid; idx < nb; idx += 256) {
        unsigned u = keys[idx];
        if (u >= tu) local += __expf(ord2f(u) - m);
    }
    red[tid] = local; __syncthreads();
    for (int k = 128; k > 0; k >>= 1) { if (tid < k) red[tid] += red[tid+k]; __syncthreads(); }
    if (tid == 0) {
        float denom = red[0] + __expf(snk - m);
        tau_o[rowid] = ord2f(tu); m_o[rowid] = m; iv_o[rowid] = 1.f / denom;
    }
}

/* ------------------------------------------------------------------ */
/* o accumulation via HMMA with register-prefetch pipeline            */
/* chunk c (0..7) handles blocks c, c+8, ..., c+56 (strided)          */
/* smem: Phi 0 | Plo 4608 | KVhi 9216 | KVlo 34816                    */
/* ------------------------------------------------------------------ */
#define AC_SMEM 60416
__global__ void __launch_bounds__(256,2) k_accum_mma(
    const float* __restrict__ kvc, const int* __restrict__ bt,
    const int* __restrict__ ctxl, const float* __restrict__ kvnew,
    const float* __restrict__ logits, const float* __restrict__ tau_i,
    const float* __restrict__ m_i, const float* __restrict__ iv_i,
    float* __restrict__ opart)
{
    extern __shared__ char sm[];
    uint32_t smb = smem_u32(sm);
    int chunk = blockIdx.x, n = blockIdx.y;
    int ctx = ctxl[n];
    int tid = threadIdx.x, wid = tid >> 5, lane = tid & 31;

    int mt = wid & 1;
    int ng = wid >> 1;
    float acc[6][4];
#pragma unroll
    for (int i = 0; i < 6; i++)
#pragma unroll
        for (int j = 0; j < 4; j++) acc[i][j] = 0.f;

    int ph = tid >> 3, pl0 = (tid & 7) * 8;
    float ptau = tau_i[n*HEADS + ph];
    float pm   = m_i[n*HEADS + ph];
    float piv  = iv_i[n*HEADS + ph];
    int kvrow = tid >> 2, kvqp = tid & 3;

    float4 kvv[12];
    float4 lsv[2];
    {
        int b = chunk, base = b * BS;
        if (base < ctx) {
            int lg = base + kvrow;
            const float* src = (lg == ctx - 1) ? (kvnew + (size_t)n*HDIM)
                                               : (kvc + ((size_t)bt[n*MAXB + b]*BS + kvrow)*HDIM);
#pragma unroll
            for (int j = 0; j < 12; j++) kvv[j] = ((const float4*)src)[kvqp * 12 + j];
            const float4* lf = (const float4*)(logits + ((size_t)(n*HEADS + ph))*LMAX + base + pl0);
            lsv[0] = lf[0]; lsv[1] = lf[1];
        }
    }

    for (int b8 = 0; b8 < 8; b8++) {
        int b = chunk + 8 * b8;
        int base = b * BS;
        if (base >= ctx) break;

        {
            float lg4[8] = {lsv[0].x, lsv[0].y, lsv[0].z, lsv[0].w,
                            lsv[1].x, lsv[1].y, lsv[1].z, lsv[1].w};
#pragma unroll
            for (int j = 0; j < 8; j += 2) {
                float p0 = (lg4[j]   >= ptau) ? (__expf(lg4[j]   - pm) * piv) : 0.f;
                float p1 = (lg4[j+1] >= ptau) ? (__expf(lg4[j+1] - pm) * piv) : 0.f;
                uint32_t hp, lp;
                split2(p0, p1, hp, lp);
                uint32_t off = (uint32_t)(ph * 144 + (pl0 + j) * 2);
                *(uint32_t*)(sm + off)        = hp;
                *(uint32_t*)(sm + 4608 + off) = lp;
            }
        }
#pragma unroll
        for (int j = 0; j < 12; j++)
            cvt_store(sm + 9216, sm + 34816,
                      (uint32_t)(kvrow * 400 + (kvqp * 12 + j) * 8), kvv[j]);
        __syncthreads();                 /* S1 */

        int bn = chunk + 8 * (b8 + 1);
        if (b8 + 1 < 8 && bn * BS < ctx) {
            int lg = bn * BS + kvrow;
            const float* src = (lg == ctx - 1) ? (kvnew + (size_t)n*HDIM)
                                               : (kvc + ((size_t)bt[n*MAXB + bn]*BS + kvrow)*HDIM);
#pragma unroll
            for (int j = 0; j < 12; j++) kvv[j] = ((const float4*)src)[kvqp * 12 + j];
            const float4* lf = (const float4*)(logits + ((size_t)(n*HEADS + ph))*LMAX + bn*BS + pl0);
            lsv[0] = lf[0]; lsv[1] = lf[1];
        }

#pragma unroll
        for (int ks = 0; ks < 4; ks++) {
            uint32_t ah[4], al[4];
            int arow = mt * 16 + (lane & 15);
            uint32_t aoff = (uint32_t)(arow * 144 + ks * 32 + (lane >> 4) * 16);
            ldm_x4(ah, smb + aoff);
            ldm_x4(al, smb + 4608 + aoff);
            int l_in = ks * 16 + ((lane >> 3) & 1) * 8 + (lane & 7);
#pragma unroll
            for (int t = 0; t < 3; t++) {
                uint32_t dByte = (uint32_t)((ng * 48 + t * 16) * 2 + ((lane >> 4) & 1) * 16);
                uint32_t boff = (uint32_t)(l_in * 400) + dByte;
                uint32_t bh[4], bl[4];
                ldm_x4t(bh, smb + 9216 + boff);
                ldm_x4t(bl, smb + 34816 + boff);
                mma16816(acc[2*t],   ah, bh);
                mma16816(acc[2*t],   ah, bl);
                mma16816(acc[2*t],   al, bh);
                mma16816(acc[2*t+1], ah, bh + 2);
                mma16816(acc[2*t+1], ah, bl + 2);
                mma16816(acc[2*t+1], al, bh + 2);
            }
        }
        __syncthreads();                 /* S2 */
    }

    float* dst = opart + ((size_t)(chunk * NB + n)) * HEADS * HDIM;
#pragma unroll
    for (int t6 = 0; t6 < 6; t6++) {
        int d = ng * 48 + t6 * 8 + (lane & 3) * 2;
        int h = mt * 16 + (lane >> 2);
        dst[(size_t)h * HDIM + d]           = acc[t6][0];
        dst[(size_t)h * HDIM + d + 1]       = acc[t6][1];
        dst[(size_t)(h + 8) * HDIM + d]     = acc[t6][2];
        dst[(size_t)(h + 8) * HDIM + d + 1] = acc[t6][3];
    }
}

/* reduce 8 o-partials -> bf16 hi/lo pairs */
__global__ void k_reduce_o(const float* __restrict__ opart,
                           __nv_bfloat16* __restrict__ ohi,
                           __nv_bfloat16* __restrict__ olo)
{
    int p = blockIdx.x*256 + threadIdx.x;
    int e0 = 2 * p;
    float v0 = 0.f, v1 = 0.f;
#pragma unroll
    for (int c = 0; c < 8; c++) {
        v0 += opart[(size_t)c*NB*QDIM + e0];
        v1 += opart[(size_t)c*NB*QDIM + e0 + 1];
    }
    uint32_t hp, lp;
    split2(v0, v1, hp, lp);
    ((uint32_t*)ohi)[p] = hp;
    ((uint32_t*)olo)[p] = lp;
}

/* ------------------------------------------------------------------ */
/* host launcher (stream fork/join during graph capture)              */
/* ------------------------------------------------------------------ */
extern "C" void kernel_launch(void* const* d_in, const int* in_sizes, int n_in,
                              void* d_out, int out_size)
{
    const float* x    = (const float*)d_in[0];
    const float* kvc  = (const float*)d_in[1];
    const int*   bt   = (const int*)  d_in[2];
    const int*   ctxl = (const int*)  d_in[3];
    const float* wqa  = (const float*)d_in[5];
    const float* qnw  = (const float*)d_in[6];
    const float* wqb  = (const float*)d_in[7];
    const float* wkv  = (const float*)d_in[8];
    const float* kvnw = (const float*)d_in[9];
    const float* woa  = (const float*)d_in[10];
    const float* wob  = (const float*)d_in[11];
    const float* sink = (const float*)d_in[12];
    float* out = (float*)d_out;

    float *kv, *lg, *tau, *mr, *iv, *op, *part;
    __nv_bfloat16 *xhi, *xlo, *qahi, *qalo, *qhi, *qlo, *oohi, *oolo, *lathi, *latlo;
    cudaGetSymbolAddress((void**)&xhi,  g_xhi);
    cudaGetSymbolAddress((void**)&xlo,  g_xlo);
    cudaGetSymbolAddress((void**)&qahi, g_qahi);
    cudaGetSymbolAddress((void**)&qalo, g_qalo);
    cudaGetSymbolAddress((void**)&kv,   g_kv);
    cudaGetSymbolAddress((void**)&qhi,  g_qhi);
    cudaGetSymbolAddress((void**)&qlo,  g_qlo);
    cudaGetSymbolAddress((void**)&lg,   g_logits);
    cudaGetSymbolAddress((void**)&tau,  g_tau);
    cudaGetSymbolAddress((void**)&mr,   g_mrow);
    cudaGetSymbolAddress((void**)&iv,   g_invden);
    cudaGetSymbolAddress((void**)&op,   g_opart);
    cudaGetSymbolAddress((void**)&oohi, g_oohi);
    cudaGetSymbolAddress((void**)&oolo, g_oolo);
    cudaGetSymbolAddress((void**)&lathi,g_lathi);
    cudaGetSymbolAddress((void**)&latlo,g_latlo);
    cudaGetSymbolAddress((void**)&part, g_part);

    static cudaStream_t s1 = 0;
    static cudaEvent_t  e0 = 0, e1 = 0;
    if (!s1) {
        cudaStreamCreateWithFlags(&s1, cudaStreamNonBlocking);
        cudaEventCreateWithFlags(&e0, cudaEventDisableTiming);
        cudaEventCreateWithFlags(&e1, cudaEventDisableTiming);
        cudaFuncSetAttribute(k_gemm_mma,   cudaFuncAttributeMaxDynamicSharedMemorySize, MM_SMEM);
        cudaFuncSetAttribute(k_logits_mma, cudaFuncAttributeMaxDynamicSharedMemorySize, LG_SMEM);
        cudaFuncSetAttribute(k_accum_mma,  cudaFuncAttributeMaxDynamicSharedMemorySize, AC_SMEM);
        cudaFuncSetAttribute(k_gemm_mma,   cudaFuncAttributePreferredSharedMemoryCarveout, 50);
        cudaFuncSetAttribute(k_logits_mma, cudaFuncAttributePreferredSharedMemoryCarveout, 76);
        cudaFuncSetAttribute(k_accum_mma,  cudaFuncAttributePreferredSharedMemoryCarveout, 55);
    }

    /* ---- x -> bf16 hi/lo ---- */
    k_x2bf<<<NB*DIMX/512, 256>>>(x, xhi, xlo);
    cudaEventRecord(e0, 0);
    cudaStreamWaitEvent(s1, e0, 0);

    /* ---- branch A (stream 0): wq_a -> rms -> wq_b -> rope/split ---- */
    k_gemm_mma<<<dim3(12, 16, 1), 256, MM_SMEM>>>(
        xhi, xlo, DIMX, 0, wqa, DIMX, 0,
        part + PART_QA_OFF, QLRK, 0, (long long)NB*QLRK, 256, QLRK);
    k_fuse_qa<<<NB, 256>>>(part + PART_QA_OFF, qnw, qahi, qalo);
    k_gemm_mma<<<dim3(48, 6, 1), 256, MM_SMEM>>>(
        qahi, qalo, QLRK, 0, wqb, QLRK, 0,
        part + PART_QB_OFF, QDIM, 0, (long long)NB*QDIM, 256, QDIM);
    k_fuse_q<<<NB, 256>>>(part + PART_QB_OFF, ctxl, qhi, qlo);

    /* ---- branch B (stream s1): wkv -> rms+rope ---- */
    k_gemm_mma<<<dim3(2, 32, 1), 256, MM_SMEM, s1>>>(
        xhi, xlo, DIMX, 0, wkv, DIMX, 0,
        part + PART_KV_OFF, HDIM, 0, (long long)NB*HDIM, 128, HDIM);
    k_fuse_kv<<<NB, 64, 0, s1>>>(part + PART_KV_OFF, kvnw, ctxl, kv);
    cudaEventRecord(e1, s1);
    cudaStreamWaitEvent(0, e1, 0);

    /* ---- attention ---- */
    k_logits_mma<<<dim3(16, NB), 256, LG_SMEM>>>(kvc, bt, ctxl, qhi, qlo, kv, lg);
    k_select<<<NB*HEADS, 256>>>(lg, sink, ctxl, tau, mr, iv);
    k_accum_mma<<<dim3(8, NB), 256, AC_SMEM>>>(kvc, bt, ctxl, kv, lg, tau, mr, iv, op);
    k_reduce_o<<<NB*QDIM/512, 256>>>(op, oohi, oolo);

    /* ---- lat = grouped wo_a : split 12 ---- */
    k_gemm_mma<<<dim3(4, 12, GRP), 256, MM_SMEM>>>(
        oohi, oolo, QDIM, 768, woa, 768, (long long)OLRK*768,
        part, GRP*OLRK, OLRK, (long long)NB*GRP*OLRK, 64, OLRK);
    k_reduce_bf<<<(NB*GRP*OLRK/2+255)/256, 256>>>(part, lathi, latlo,
                                                  NB*GRP*OLRK/2, NB*GRP*OLRK, 12);

    /* ---- out = lat @ wo_b^T : split 16 ---- */
    k_gemm_mma<<<dim3(32, 16, 1), 256, MM_SMEM>>>(
        lathi, latlo, GRP*OLRK, 0, wob, DIMX, 0,
        part, DIMX, 0, (long long)NB*DIMX, 256, DIMX);
    k_reduce<<<(NB*DIMX+255)/256, 256>>>(part, out, NB*DIMX, 16);
}

// round 17
// speedup vs baseline: 1.1031x; 1.0130x over previous
#include <cuda_runtime.h>
#include <cuda_bf16.h>
#include <math.h>
#include <stdint.h>

#define NB    64
#define DIMX  4096
#define HEADS 32
#define HDIM  192
#define RDIM  64
#define QLRK  1536
#define OLRK  512
#define GRP   8
#define BS    64
#define MAXB  64
#define LMAX  4096
#define TOPKK 1024
#define EPSI  1e-6f
#define NEGF  -1e30f
#define QDIM  (HEADS*HDIM)   /* 6144 */
#define SCALE_F 0.07216878364870323f  /* 192^-0.5 */

/* disjoint split-K partial regions (floats) */
#define PART_QA_OFF 0                         /* 16*98304  = 1572864 */
#define PART_KV_OFF 1572864                   /* 32*12288  = 393216  */
#define PART_QB_OFF 1966080                   /* 6*393216  = 2359296 */
#define PART_TOTAL  4325376                   /* 16.5 MB */

/* ------------------------------------------------------------------ */
/* scratch                                                            */
/* ------------------------------------------------------------------ */
__device__ __nv_bfloat16 g_xhi[NB*DIMX];
__device__ __nv_bfloat16 g_xlo[NB*DIMX];
__device__ __nv_bfloat16 g_qahi[NB*QLRK];
__device__ __nv_bfloat16 g_qalo[NB*QLRK];
__device__ float g_kv[NB*HDIM];
__device__ __nv_bfloat16 g_qhi[NB*QDIM];
__device__ __nv_bfloat16 g_qlo[NB*QDIM];
__device__ float g_logits[(size_t)NB*HEADS*LMAX];       /* 32 MB */
__device__ float g_tau[NB*HEADS];
__device__ float g_mrow[NB*HEADS];
__device__ float g_invden[NB*HEADS];
__device__ float g_opart[(size_t)8*NB*HEADS*HDIM];      /* 12.6 MB */
__device__ __nv_bfloat16 g_oohi[NB*QDIM];
__device__ __nv_bfloat16 g_oolo[NB*QDIM];
__device__ __nv_bfloat16 g_lathi[NB*GRP*OLRK];
__device__ __nv_bfloat16 g_latlo[NB*GRP*OLRK];
__device__ float g_part[PART_TOTAL];

/* ------------------------------------------------------------------ */
/* helpers                                                            */
/* ------------------------------------------------------------------ */
__device__ __forceinline__ uint32_t smem_u32(const void* p){
    uint32_t a;
    asm("{ .reg .u64 t; cvta.to.shared.u64 t, %1; cvt.u32.u64 %0, t; }"
        : "=r"(a) : "l"(p));
    return a;
}
__device__ __forceinline__ uint32_t sw128(uint32_t b){ return b ^ ((b >> 3) & 0x70); }

/* fast exact split: hi = truncate-to-bf16 (bit prefix), lo = rn(v-hi). */
__device__ __forceinline__ void split2(float x, float y, uint32_t& hp, uint32_t& lp){
    uint32_t bx = __float_as_uint(x), by = __float_as_uint(y);
    uint32_t h;
    asm("prmt.b32 %0, %1, %2, 0x7632;" : "=r"(h) : "r"(bx), "r"(by));
    float fx = __uint_as_float(h << 16);
    float fy = __uint_as_float(h & 0xFFFF0000u);
    float lx = x - fx, ly = y - fy;
    uint32_t l;
    asm("cvt.rn.bf16x2.f32 %0, %1, %2;" : "=r"(l) : "f"(ly), "f"(lx));
    hp = h; lp = l;
}
__device__ __forceinline__ void mma16816(float* c, const uint32_t* a, const uint32_t* b){
    asm volatile("mma.sync.aligned.m16n8k16.row.col.f32.bf16.bf16.f32 "
        "{%0,%1,%2,%3}, {%4,%5,%6,%7}, {%8,%9}, {%0,%1,%2,%3};"
        : "+f"(c[0]), "+f"(c[1]), "+f"(c[2]), "+f"(c[3])
        : "r"(a[0]), "r"(a[1]), "r"(a[2]), "r"(a[3]), "r"(b[0]), "r"(b[1]));
}
__device__ __forceinline__ void ldm_x4(uint32_t* r, uint32_t addr){
    asm volatile("ldmatrix.sync.aligned.m8n8.x4.shared.b16 {%0,%1,%2,%3}, [%4];"
        : "=r"(r[0]), "=r"(r[1]), "=r"(r[2]), "=r"(r[3]) : "r"(addr));
}
__device__ __forceinline__ void ldm_x4t(uint32_t* r, uint32_t addr){
    asm volatile("ldmatrix.sync.aligned.m8n8.x4.trans.shared.b16 {%0,%1,%2,%3}, [%4];"
        : "=r"(r[0]), "=r"(r[1]), "=r"(r[2]), "=r"(r[3]) : "r"(addr));
}
__device__ __forceinline__ void cvt_store(char* hiB, char* loB, uint32_t off, float4 v){
    uint2 hh, ll;
    split2(v.x, v.y, hh.x, ll.x);
    split2(v.z, v.w, hh.y, ll.y);
    *(uint2*)(hiB + off) = hh;
    *(uint2*)(loB + off) = ll;
}

/* ------------------------------------------------------------------ */
/* HMMA GEMM (round-12 best config: single stage, warp tile 32x32)    */
/* ------------------------------------------------------------------ */
#define MM_SMEM 49152
__global__ void __launch_bounds__(256,2) k_gemm_mma(
    const __nv_bfloat16* __restrict__ Xhi, const __nv_bfloat16* __restrict__ Xlo,
    int ldx, long long xGrp,
    const float* __restrict__ W, int ldw, long long wGrp,
    float* __restrict__ C, int ldc, long long cGrp, long long cSplit,
    int Kloc, int Nw)
{
    extern __shared__ char sm[];
    char* sXhi = sm;
    char* sXlo = sm + 8192;
    char* sWhi = sm + 16384;
    char* sWlo = sm + 32768;
    uint32_t smb = smem_u32(sm);

    int tid = threadIdx.x, wid = tid >> 5, lane = tid & 31;
    int n0 = blockIdx.x * 128;
    int s  = blockIdx.y;
    int g  = blockIdx.z;
    Xhi += (size_t)g * xGrp + (size_t)s * Kloc;
    Xlo += (size_t)g * xGrp + (size_t)s * Kloc;
    W   += (size_t)g * wGrp + (size_t)s * Kloc;
    C   += (size_t)g * cGrp + (size_t)s * cSplit;

    int wm = (wid & 1) * 32;
    int wn = (wid >> 1) * 32;

    float acc[8][4];
#pragma unroll
    for (int i = 0; i < 8; i++)
#pragma unroll
        for (int j = 0; j < 4; j++) acc[i][j] = 0.f;

    int xr0 = tid >> 3, xr1 = (tid + 256) >> 3;
    int xc16 = tid & 7;
    int wrow = tid >> 1;
    int wc   = tid & 1;
    int wrg  = n0 + wrow; if (wrg >= Nw) wrg = Nw - 1;

    const int NC = Kloc / 64;
    uint4 xh[2], xl[2];
    float4 wv[8];
    xh[0] = *(const uint4*)(Xhi + (size_t)xr0 * ldx + xc16 * 8);
    xh[1] = *(const uint4*)(Xhi + (size_t)xr1 * ldx + xc16 * 8);
    xl[0] = *(const uint4*)(Xlo + (size_t)xr0 * ldx + xc16 * 8);
    xl[1] = *(const uint4*)(Xlo + (size_t)xr1 * ldx + xc16 * 8);
#pragma unroll
    for (int j = 0; j < 8; j++)
        wv[j] = *(const float4*)(W + (size_t)wrg * ldw + (wc + 2*j) * 4);

    for (int ch = 0; ch < NC; ch++) {
        if (ch) __syncthreads();
        {
            uint32_t o0 = sw128((uint32_t)(xr0 * 128 + xc16 * 16));
            uint32_t o1 = sw128((uint32_t)(xr1 * 128 + xc16 * 16));
            *(uint4*)(sXhi + o0) = xh[0];
            *(uint4*)(sXhi + o1) = xh[1];
            *(uint4*)(sXlo + o0) = xl[0];
            *(uint4*)(sXlo + o1) = xl[1];
        }
#pragma unroll
        for (int j = 0; j < 8; j++) {
            uint32_t off = sw128((uint32_t)(wrow * 128 + (wc + 2*j) * 8));
            cvt_store(sWhi, sWlo, off, wv[j]);
        }
        __syncthreads();
        if (ch + 1 < NC) {
            int kb = (ch + 1) * 64;
            xh[0] = *(const uint4*)(Xhi + (size_t)xr0 * ldx + kb + xc16 * 8);
            xh[1] = *(const uint4*)(Xhi + (size_t)xr1 * ldx + kb + xc16 * 8);
            xl[0] = *(const uint4*)(Xlo + (size_t)xr0 * ldx + kb + xc16 * 8);
            xl[1] = *(const uint4*)(Xlo + (size_t)xr1 * ldx + kb + xc16 * 8);
#pragma unroll
            for (int j = 0; j < 8; j++)
                wv[j] = *(const float4*)(W + (size_t)wrg * ldw + kb + (wc + 2*j) * 4);
        }
#pragma unroll
        for (int ks = 0; ks < 4; ks++) {
            uint32_t ah[2][4], al[2][4];
#pragma unroll
            for (int mtq = 0; mtq < 2; mtq++) {
                int arow = wm + mtq * 16 + (lane & 15);
                uint32_t aoff = sw128((uint32_t)(arow * 128 + (ks*2 + (lane >> 4)) * 16));
                ldm_x4(ah[mtq], smb + aoff);
                ldm_x4(al[mtq], smb + 8192 + aoff);
            }
#pragma unroll
            for (int t = 0; t < 2; t++) {
                int brow = wn + 16*t + ((lane >> 4) & 1) * 8 + (lane & 7);
                uint32_t boff = sw128((uint32_t)(brow * 128 + (ks*2 + ((lane >> 3) & 1)) * 16));
                uint32_t bh[4], bl[4];
                ldm_x4(bh, smb + 16384 + boff);
                ldm_x4(bl, smb + 32768 + boff);
#pragma unroll
                for (int mtq = 0; mtq < 2; mtq++) {
                    float* a0 = acc[mtq*4 + t*2];
                    float* a1 = acc[mtq*4 + t*2 + 1];
                    mma16816(a0, ah[mtq], bh);
                    mma16816(a0, ah[mtq], bl);
                    mma16816(a0, al[mtq], bh);
                    mma16816(a1, ah[mtq], bh + 2);
                    mma16816(a1, ah[mtq], bl + 2);
                    mma16816(a1, al[mtq], bh + 2);
                }
            }
        }
    }

#pragma unroll
    for (int mtq = 0; mtq < 2; mtq++) {
        int mr = wm + mtq * 16 + (lane >> 2);
#pragma unroll
        for (int sub = 0; sub < 4; sub++) {
            int nc = n0 + wn + sub * 8 + (lane & 3) * 2;
            float* a = acc[mtq*4 + sub];
            if (nc < Nw) {
                C[(size_t)mr * ldc + nc]       = a[0];
                C[(size_t)(mr + 8) * ldc + nc] = a[2];
            }
            if (nc + 1 < Nw) {
                C[(size_t)mr * ldc + nc + 1]       = a[1];
                C[(size_t)(mr + 8) * ldc + nc + 1] = a[3];
            }
        }
    }
}

/* generic split-K reduce -> fp32 */
__global__ void k_reduce(const float* __restrict__ part, float* __restrict__ out,
                         int E, int S)
{
    int i = blockIdx.x * 256 + threadIdx.x;
    if (i >= E) return;
    float s = 0.f;
    for (int p = 0; p < S; p++) s += part[(size_t)p * E + i];
    out[i] = s;
}

/* split-K reduce -> bf16 hi/lo pairs */
__global__ void k_reduce_bf(const float* __restrict__ part,
                            __nv_bfloat16* __restrict__ ohi,
                            __nv_bfloat16* __restrict__ olo,
                            int Epairs, int E, int S)
{
    int p = blockIdx.x * 256 + threadIdx.x;
    if (p >= Epairs) return;
    int e0 = 2 * p;
    float v0 = 0.f, v1 = 0.f;
    for (int q = 0; q < S; q++) {
        v0 += part[(size_t)q * E + e0];
        v1 += part[(size_t)q * E + e0 + 1];
    }
    uint32_t hp, lp;
    split2(v0, v1, hp, lp);
    ((uint32_t*)ohi)[p] = hp;
    ((uint32_t*)olo)[p] = lp;
}

/* x fp32 -> bf16 hi/lo */
__global__ void __launch_bounds__(256) k_x2bf(const float* __restrict__ x,
                                              __nv_bfloat16* __restrict__ xhi,
                                              __nv_bfloat16* __restrict__ xlo)
{
    int p = blockIdx.x * 256 + threadIdx.x;
    float2 v = ((const float2*)x)[p];
    uint32_t hp, lp;
    split2(v.x, v.y, hp, lp);
    ((uint32_t*)xhi)[p] = hp;
    ((uint32_t*)xlo)[p] = lp;
}

/* ------------------------------------------------------------------ */
/* fused: reduce 16 partials + RMS(q_norm) -> bf16 hi/lo              */
/* ------------------------------------------------------------------ */
__global__ void __launch_bounds__(256) k_fuse_qa(const float* __restrict__ part,
                                                 const float* __restrict__ wt,
                                                 __nv_bfloat16* __restrict__ qahi,
                                                 __nv_bfloat16* __restrict__ qalo)
{
    __shared__ float red[256];
    int n = blockIdx.x, tid = threadIdx.x;
    float v0[3], v1[3]; float s = 0.f;
#pragma unroll
    for (int i = 0; i < 3; i++) {
        int e0 = 2 * (tid + i*256);
        float a = 0.f, b = 0.f;
#pragma unroll
        for (int p = 0; p < 16; p++) {
            a += part[(size_t)p*NB*QLRK + (size_t)n*QLRK + e0];
            b += part[(size_t)p*NB*QLRK + (size_t)n*QLRK + e0 + 1];
        }
        v0[i] = a; v1[i] = b; s += a*a + b*b;
    }
    red[tid] = s; __syncthreads();
    for (int k = 128; k > 0; k >>= 1) { if (tid < k) red[tid] += red[tid+k]; __syncthreads(); }
    float scale = rsqrtf(red[0] / (float)QLRK + EPSI);
#pragma unroll
    for (int i = 0; i < 3; i++) {
        int p = tid + i*256;
        int e0 = 2 * p;
        float f0 = v0[i] * scale * wt[e0];
        float f1 = v1[i] * scale * wt[e0 + 1];
        uint32_t hp, lp;
        split2(f0, f1, hp, lp);
        ((uint32_t*)qahi)[(size_t)n*(QLRK/2) + p] = hp;
        ((uint32_t*)qalo)[(size_t)n*(QLRK/2) + p] = lp;
    }
}

__device__ __forceinline__ void rope_cs(int i, float pos, float& c, float& s)
{
    float inv = (float)exp(-(double)i * 0.28782313662425574); /* ln(1e4)/32 */
    float ang = pos * inv;
    double ad = (double)ang;
    c = (float)cos(ad); s = (float)sin(ad);
}

/* fused: reduce 32 partials + RMS + rope -> g_kv (fp32)              */
__global__ void k_fuse_kv(const float* __restrict__ part,
                          const float* __restrict__ wt,
                          const int* __restrict__ ctxl,
                          float* __restrict__ kv)
{
    __shared__ float srow[HDIM];
    __shared__ float rs[64];
    int n = blockIdx.x, tid = threadIdx.x;
    float s = 0.f;
#pragma unroll
    for (int j = 0; j < 3; j++) {
        int c = tid + j*64;
        float t = 0.f;
#pragma unroll
        for (int p = 0; p < 32; p++) t += part[(size_t)p*NB*HDIM + (size_t)n*HDIM + c];
        srow[c] = t; s += t*t;
    }
    rs[tid] = s; __syncthreads();
    for (int k = 32; k > 0; k >>= 1) { if (tid < k) rs[tid] += rs[tid+k]; __syncthreads(); }
    float scale = rsqrtf(rs[0] / (float)HDIM + EPSI);
#pragma unroll
    for (int j = 0; j < 3; j++) { int i = tid + j*64; srow[i] = srow[i]*scale*wt[i]; }
    __syncthreads();
    float pos = (float)(ctxl[n] - 1);
    if (tid < 32) {
        int i = tid;
        float x0 = srow[HDIM-RDIM + 2*i], x1 = srow[HDIM-RDIM + 2*i + 1];
        float c, sn; rope_cs(i, pos, c, sn);
        srow[HDIM-RDIM + 2*i]     = x0*c - x1*sn;
        srow[HDIM-RDIM + 2*i + 1] = x0*sn + x1*c;
    }
    __syncthreads();
#pragma unroll
    for (int j = 0; j < 3; j++) { int i = tid + j*64; kv[(size_t)n*HDIM + i] = srow[i]; }
}

/* fused: reduce 6 partials + rope + bf16 split -> g_qhi/g_qlo        */
__global__ void __launch_bounds__(256) k_fuse_q(const float* __restrict__ part,
                                                const int* __restrict__ ctxl,
                                                __nv_bfloat16* __restrict__ qhi,
                                                __nv_bfloat16* __restrict__ qlo)
{
    int n = blockIdx.x, tid = threadIdx.x;
    float pos = (float)(ctxl[n] - 1);
#pragma unroll
    for (int i = 0; i < 12; i++) {
        int p = tid + i*256;
        int e0 = 2*p;
        float v0 = 0.f, v1 = 0.f;
#pragma unroll
        for (int q = 0; q < 6; q++) {
            v0 += part[(size_t)q*NB*QDIM + (size_t)n*QDIM + e0];
            v1 += part[(size_t)q*NB*QDIM + (size_t)n*QDIM + e0 + 1];
        }
        int dd = e0 % HDIM;
        if (dd >= HDIM - RDIM) {
            int ir = (dd - (HDIM - RDIM)) >> 1;
            float c, s; rope_cs(ir, pos, c, s);
            float x0 = v0, x1 = v1;
            v0 = x0*c - x1*s;
            v1 = x0*s + x1*c;
        }
        uint32_t hp, lp;
        split2(v0, v1, hp, lp);
        ((uint32_t*)qhi)[(size_t)n*(QDIM/2) + p] = hp;
        ((uint32_t*)qlo)[(size_t)n*(QDIM/2) + p] = lp;
    }
}

/* ------------------------------------------------------------------ */
/* logits via HMMA with register-prefetch KV pipeline                 */
/* CTA bx (0..15) handles blocks bx, bx+16, bx+32, bx+48 (strided)    */
/* smem: Qhi 0 | Qlo 12800 | KVhi 25600 | KVlo 51200 | D 76800        */
/* ------------------------------------------------------------------ */
#define LG_SMEM 84992
__global__ void __launch_bounds__(256,2) k_logits_mma(
    const float* __restrict__ kvc, const int* __restrict__ bt,
    const int* __restrict__ ctxl,
    const __nv_bfloat16* __restrict__ qhi, const __nv_bfloat16* __restrict__ qlo,
    const float* __restrict__ kvnew, float* __restrict__ logits)
{
    extern __shared__ char sm[];
    uint32_t smb = smem_u32(sm);
    int n = blockIdx.y;
    int ctx = ctxl[n];
    int bx = blockIdx.x;               /* 0..15 */
    if (bx * BS >= ctx) return;
    int tid = threadIdx.x, wid = tid >> 5, lane = tid & 31;

    {
        const char* gh = (const char*)(qhi + (size_t)n * QDIM);
        const char* gl = (const char*)(qlo + (size_t)n * QDIM);
#pragma unroll
        for (int i = 0; i < 3; i++) {
            int c = tid + i * 256;
            int r = c / 24, k16 = c % 24;
            *(uint4*)(sm + r * 400 + k16 * 16) = *(const uint4*)(gh + r * 384 + k16 * 16);
            *(uint4*)(sm + 12800 + r * 400 + k16 * 16) = *(const uint4*)(gl + r * 384 + k16 * 16);
        }
    }

    int mt = wid & 3;
    int nt = wid >> 2;
    int kvrow = tid >> 2, kvqp = tid & 3;

    float4 kvv[12];
    {   /* prefetch block bx */
        int lg = bx * BS + kvrow;
        const float* src = (lg == ctx - 1) ? (kvnew + (size_t)n * HDIM)
                                           : (kvc + ((size_t)bt[n*MAXB + bx] * BS + kvrow) * HDIM);
#pragma unroll
        for (int j = 0; j < 12; j++) kvv[j] = ((const float4*)src)[kvqp * 12 + j];
    }

    for (int bi = 0; bi < 4; bi++) {
        int b = bx + 16 * bi;
        int base = b * BS;
        if (base >= ctx) break;

#pragma unroll
        for (int j = 0; j < 12; j++)
            cvt_store(sm + 25600, sm + 51200,
                      (uint32_t)(kvrow * 400 + (kvqp * 12 + j) * 8), kvv[j]);
        __syncthreads();                 /* S1 */

        int bnext = bx + 16 * (bi + 1);
        if (bi + 1 < 4 && bnext * BS < ctx) {
            int lg = bnext * BS + kvrow;
            const float* src = (lg == ctx - 1) ? (kvnew + (size_t)n * HDIM)
                                               : (kvc + ((size_t)bt[n*MAXB + bnext] * BS + kvrow) * HDIM);
#pragma unroll
            for (int j = 0; j < 12; j++) kvv[j] = ((const float4*)src)[kvqp * 12 + j];
        }

        float acc[2][4];
#pragma unroll
        for (int i = 0; i < 2; i++)
#pragma unroll
            for (int j = 0; j < 4; j++) acc[i][j] = 0.f;

#pragma unroll
        for (int ks = 0; ks < 12; ks++) {
            uint32_t ah[4], al[4];
            int arow = mt * 16 + (lane & 15);
            uint32_t aoff = (uint32_t)(arow * 400 + ks * 32 + (lane >> 4) * 16);
            ldm_x4(ah, smb + 25600 + aoff);
            ldm_x4(al, smb + 51200 + aoff);
            int brow = nt * 16 + ((lane >> 4) & 1) * 8 + (lane & 7);
            uint32_t boff = (uint32_t)(brow * 400 + ks * 32 + ((lane >> 3) & 1) * 16);
            uint32_t bh[4], bl[4];
            ldm_x4(bh, smb + boff);
            ldm_x4(bl, smb + 12800 + boff);
            mma16816(acc[0], ah, bh);
            mma16816(acc[0], ah, bl);
            mma16816(acc[0], al, bh);
            mma16816(acc[1], ah, bh + 2);
            mma16816(acc[1], ah, bl + 2);
            mma16816(acc[1], al, bh + 2);
        }

        float* D = (float*)(sm + 76800);
#pragma unroll
        for (int n8 = 0; n8 < 2; n8++) {
            int h = nt * 16 + n8 * 8 + (lane & 3) * 2;
            int l = mt * 16 + (lane >> 2);
            D[h * 64 + l]           = acc[n8][0];
            D[(h + 1) * 64 + l]     = acc[n8][1];
            D[h * 64 + l + 8]       = acc[n8][2];
            D[(h + 1) * 64 + l + 8] = acc[n8][3];
        }
        __syncthreads();                 /* S2 */

        /* vectorized epilogue: 2x STG.128 per thread */
        int h = tid >> 3, l0 = (tid & 7) * 8;
        float* dst = logits + ((size_t)(n * HEADS + h)) * LMAX + base + l0;
        float4 o0, o1;
        {
            const float* Drow = D + h * 64 + l0;
            o0.x = (base + l0 + 0 < ctx) ? Drow[0] * SCALE_F : NEGF;
            o0.y = (base + l0 + 1 < ctx) ? Drow[1] * SCALE_F : NEGF;
            o0.z = (base + l0 + 2 < ctx) ? Drow[2] * SCALE_F : NEGF;
            o0.w = (base + l0 + 3 < ctx) ? Drow[3] * SCALE_F : NEGF;
            o1.x = (base + l0 + 4 < ctx) ? Drow[4] * SCALE_F : NEGF;
            o1.y = (base + l0 + 5 < ctx) ? Drow[5] * SCALE_F : NEGF;
            o1.z = (base + l0 + 6 < ctx) ? Drow[6] * SCALE_F : NEGF;
            o1.w = (base + l0 + 7 < ctx) ? Drow[7] * SCALE_F : NEGF;
        }
        *(float4*)dst       = o0;
        *(float4*)(dst + 4) = o1;
    }
}

/* ------------------------------------------------------------------ */
/* top-k radix select: keys register-resident (no smem key buffer)    */
/* ------------------------------------------------------------------ */
__device__ __forceinline__ unsigned f2ord(float f) {
    unsigned b = __float_as_uint(f);
    return (b & 0x80000000u) ? ~b : (b | 0x80000000u);
}
__device__ __forceinline__ float ord2f(unsigned u) {
    return (u & 0x80000000u) ? __uint_as_float(u ^ 0x80000000u)
                             : __uint_as_float(~u);
}

__global__ void __launch_bounds__(256) k_select(
    const float* __restrict__ logits, const float* __restrict__ sink,
    const int* __restrict__ ctxl,
    float* __restrict__ tau_o, float* __restrict__ m_o, float* __restrict__ iv_o)
{
    __shared__ unsigned hist[256];
    __shared__ unsigned wsum[8];
    __shared__ unsigned rmax[256];
    __shared__ float    red[256];
    __shared__ unsigned s_prefix;
    __shared__ int      s_k;

    int rowid = blockIdx.x;
    int n = rowid >> 5;
    int h = rowid & 31;
    int tid = threadIdx.x;
    int w = tid >> 5, l = tid & 31;
    int ctx = ctxl[n];
    int nb = ((ctx + 63) >> 6) << 6;
    const float* src = logits + (size_t)rowid * LMAX;

    /* keys in registers: thread owns idx = tid + i*256; invalid -> 0
       (key 0 is below any reachable threshold: all in-range slots hold
        real logits or the NEG filler whose ordered key is ~0x0ED...) */
    unsigned kr[16];
    int ni = (nb - tid + 255) >> 8;
    unsigned um = 0u;
#pragma unroll
    for (int i = 0; i < 16; i++) {
        unsigned u = 0u;
        if (i < ni) u = f2ord(src[tid + i * 256]);
        kr[i] = u;
        um = max(um, u);
    }
    rmax[tid] = um; __syncthreads();
    for (int k = 128; k > 0; k >>= 1) { if (tid < k) rmax[tid] = max(rmax[tid], rmax[tid+k]); __syncthreads(); }

    float maxf = ord2f(rmax[0]);
    float snk  = sink[h];
    float m    = fmaxf(maxf, snk);

    if (nb <= TOPKK) {
        float local = 0.f;
#pragma unroll
        for (int i = 0; i < 16; i++)
            if (i < ni) local += __expf(ord2f(kr[i]) - m);
        red[tid] = local; __syncthreads();
        for (int k = 128; k > 0; k >>= 1) { if (tid < k) red[tid] += red[tid+k]; __syncthreads(); }
        if (tid == 0) {
            float denom = red[0] + __expf(snk - m);
            tau_o[rowid] = -__builtin_huge_valf(); m_o[rowid] = m; iv_o[rowid] = 1.f / denom;
        }
        return;
    }

    if (tid == 0) { s_prefix = 0u; s_k = TOPKK; }
    __syncthreads();

    for (int shift = 24; shift >= 0; shift -= 8) {
        hist[tid] = 0u;
        __syncthreads();
        unsigned pref = s_prefix;
        int kk = s_k;
        unsigned himask = (shift == 24) ? 0u : (0xFFFFFFFFu << (shift + 8));
#pragma unroll
        for (int i = 0; i < 16; i++) {
            unsigned u = kr[i];
            if (i < ni && (u & himask) == pref) atomicAdd(&hist[(u >> shift) & 255u], 1u);
        }
        __syncthreads();
        /* warp-shuffle inclusive suffix scan over 256 bins */
        unsigned hv = hist[tid];
        unsigned v  = hv;
#pragma unroll
        for (int st = 1; st < 32; st <<= 1) {
            unsigned t = __shfl_down_sync(0xFFFFFFFFu, v, st);
            if (l + st < 32) v += t;
        }
        if (l == 0) wsum[w] = v;
        __syncthreads();
        unsigned add = 0u;
#pragma unroll
        for (int q = 0; q < 8; q++)
            if (q > w) add += wsum[q];
        unsigned Sb = v + add;
        unsigned Sn = Sb - hv;
        if (Sb >= (unsigned)kk && Sn < (unsigned)kk) {
            s_prefix = pref | ((unsigned)tid << shift);
            s_k = kk - (int)Sn;
        }
        __syncthreads();
    }
    unsigned tu = s_prefix;

    float local = 0.f;
#pragma unroll
    for (int i = 0; i < 16; i++) {
        unsigned u = kr[i];
        if (u >= tu) local += __expf(ord2f(u) - m);
    }
    red[tid] = local; __syncthreads();
    for (int k = 128; k > 0; k >>= 1) { if (tid < k) red[tid] += red[tid+k]; __syncthreads(); }
    if (tid == 0) {
        float denom = red[0] + __expf(snk - m);
        tau_o[rowid] = ord2f(tu); m_o[rowid] = m; iv_o[rowid] = 1.f / denom;
    }
}

/* ------------------------------------------------------------------ */
/* o accumulation via HMMA with register-prefetch pipeline            */
/* chunk c (0..7) handles blocks c, c+8, ..., c+56 (strided)          */
/* smem: Phi 0 | Plo 4608 | KVhi 9216 | KVlo 34816                    */
/* ------------------------------------------------------------------ */
#define AC_SMEM 60416
__global__ void __launch_bounds__(256,2) k_accum_mma(
    const float* __restrict__ kvc, const int* __restrict__ bt,
    const int* __restrict__ ctxl, const float* __restrict__ kvnew,
    const float* __restrict__ logits, const float* __restrict__ tau_i,
    const float* __restrict__ m_i, const float* __restrict__ iv_i,
    float* __restrict__ opart)
{
    extern __shared__ char sm[];
    uint32_t smb = smem_u32(sm);
    int chunk = blockIdx.x, n = blockIdx.y;
    int ctx = ctxl[n];
    int tid = threadIdx.x, wid = tid >> 5, lane = tid & 31;

    int mt = wid & 1;
    int ng = wid >> 1;
    float acc[6][4];
#pragma unroll
    for (int i = 0; i < 6; i++)
#pragma unroll
        for (int j = 0; j < 4; j++) acc[i][j] = 0.f;

    int ph = tid >> 3, pl0 = (tid & 7) * 8;
    float ptau = tau_i[n*HEADS + ph];
    float pm   = m_i[n*HEADS + ph];
    float piv  = iv_i[n*HEADS + ph];
    int kvrow = tid >> 2, kvqp = tid & 3;

    float4 kvv[12];
    float4 lsv[2];
    {
        int b = chunk, base = b * BS;
        if (base < ctx) {
            int lg = base + kvrow;
            const float* src = (lg == ctx - 1) ? (kvnew + (size_t)n*HDIM)
                                               : (kvc + ((size_t)bt[n*MAXB + b]*BS + kvrow)*HDIM);
#pragma unroll
            for (int j = 0; j < 12; j++) kvv[j] = ((const float4*)src)[kvqp * 12 + j];
            const float4* lf = (const float4*)(logits + ((size_t)(n*HEADS + ph))*LMAX + base + pl0);
            lsv[0] = lf[0]; lsv[1] = lf[1];
        }
    }

    for (int b8 = 0; b8 < 8; b8++) {
        int b = chunk + 8 * b8;
        int base = b * BS;
        if (base >= ctx) break;

        {
            float lg4[8] = {lsv[0].x, lsv[0].y, lsv[0].z, lsv[0].w,
                            lsv[1].x, lsv[1].y, lsv[1].z, lsv[1].w};
#pragma unroll
            for (int j = 0; j < 8; j += 2) {
                float p0 = (lg4[j]   >= ptau) ? (__expf(lg4[j]   - pm) * piv) : 0.f;
                float p1 = (lg4[j+1] >= ptau) ? (__expf(lg4[j+1] - pm) * piv) : 0.f;
                uint32_t hp, lp;
                split2(p0, p1, hp, lp);
                uint32_t off = (uint32_t)(ph * 144 + (pl0 + j) * 2);
                *(uint32_t*)(sm + off)        = hp;
                *(uint32_t*)(sm + 4608 + off) = lp;
            }
        }
#pragma unroll
        for (int j = 0; j < 12; j++)
            cvt_store(sm + 9216, sm + 34816,
                      (uint32_t)(kvrow * 400 + (kvqp * 12 + j) * 8), kvv[j]);
        __syncthreads();                 /* S1 */

        int bn = chunk + 8 * (b8 + 1);
        if (b8 + 1 < 8 && bn * BS < ctx) {
            int lg = bn * BS + kvrow;
            const float* src = (lg == ctx - 1) ? (kvnew + (size_t)n*HDIM)
                                               : (kvc + ((size_t)bt[n*MAXB + bn]*BS + kvrow)*HDIM);
#pragma unroll
            for (int j = 0; j < 12; j++) kvv[j] = ((const float4*)src)[kvqp * 12 + j];
            const float4* lf = (const float4*)(logits + ((size_t)(n*HEADS + ph))*LMAX + bn*BS + pl0);
            lsv[0] = lf[0]; lsv[1] = lf[1];
        }

#pragma unroll
        for (int ks = 0; ks < 4; ks++) {
            uint32_t ah[4], al[4];
            int arow = mt * 16 + (lane & 15);
            uint32_t aoff = (uint32_t)(arow * 144 + ks * 32 + (lane >> 4) * 16);
            ldm_x4(ah, smb + aoff);
            ldm_x4(al, smb + 4608 + aoff);
            int l_in = ks * 16 + ((lane >> 3) & 1) * 8 + (lane & 7);
#pragma unroll
            for (int t = 0; t < 3; t++) {
                uint32_t dByte = (uint32_t)((ng * 48 + t * 16) * 2 + ((lane >> 4) & 1) * 16);
                uint32_t boff = (uint32_t)(l_in * 400) + dByte;
                uint32_t bh[4], bl[4];
                ldm_x4t(bh, smb + 9216 + boff);
                ldm_x4t(bl, smb + 34816 + boff);
                mma16816(acc[2*t],   ah, bh);
                mma16816(acc[2*t],   ah, bl);
                mma16816(acc[2*t],   al, bh);
                mma16816(acc[2*t+1], ah, bh + 2);
                mma16816(acc[2*t+1], ah, bl + 2);
                mma16816(acc[2*t+1], al, bh + 2);
            }
        }
        __syncthreads();                 /* S2 */
    }

    float* dst = opart + ((size_t)(chunk * NB + n)) * HEADS * HDIM;
#pragma unroll
    for (int t6 = 0; t6 < 6; t6++) {
        int d = ng * 48 + t6 * 8 + (lane & 3) * 2;
        int h = mt * 16 + (lane >> 2);
        dst[(size_t)h * HDIM + d]           = acc[t6][0];
        dst[(size_t)h * HDIM + d + 1]       = acc[t6][1];
        dst[(size_t)(h + 8) * HDIM + d]     = acc[t6][2];
        dst[(size_t)(h + 8) * HDIM + d + 1] = acc[t6][3];
    }
}

/* reduce 8 o-partials -> bf16 hi/lo pairs */
__global__ void k_reduce_o(const float* __restrict__ opart,
                           __nv_bfloat16* __restrict__ ohi,
                           __nv_bfloat16* __restrict__ olo)
{
    int p = blockIdx.x*256 + threadIdx.x;
    int e0 = 2 * p;
    float v0 = 0.f, v1 = 0.f;
#pragma unroll
    for (int c = 0; c < 8; c++) {
        v0 += opart[(size_t)c*NB*QDIM + e0];
        v1 += opart[(size_t)c*NB*QDIM + e0 + 1];
    }
    uint32_t hp, lp;
    split2(v0, v1, hp, lp);
    ((uint32_t*)ohi)[p] = hp;
    ((uint32_t*)olo)[p] = lp;
}

/* ------------------------------------------------------------------ */
/* host launcher (stream fork/join during graph capture)              */
/* ------------------------------------------------------------------ */
extern "C" void kernel_launch(void* const* d_in, const int* in_sizes, int n_in,
                              void* d_out, int out_size)
{
    const float* x    = (const float*)d_in[0];
    const float* kvc  = (const float*)d_in[1];
    const int*   bt   = (const int*)  d_in[2];
    const int*   ctxl = (const int*)  d_in[3];
    const float* wqa  = (const float*)d_in[5];
    const float* qnw  = (const float*)d_in[6];
    const float* wqb  = (const float*)d_in[7];
    const float* wkv  = (const float*)d_in[8];
    const float* kvnw = (const float*)d_in[9];
    const float* woa  = (const float*)d_in[10];
    const float* wob  = (const float*)d_in[11];
    const float* sink = (const float*)d_in[12];
    float* out = (float*)d_out;

    float *kv, *lg, *tau, *mr, *iv, *op, *part;
    __nv_bfloat16 *xhi, *xlo, *qahi, *qalo, *qhi, *qlo, *oohi, *oolo, *lathi, *latlo;
    cudaGetSymbolAddress((void**)&xhi,  g_xhi);
    cudaGetSymbolAddress((void**)&xlo,  g_xlo);
    cudaGetSymbolAddress((void**)&qahi, g_qahi);
    cudaGetSymbolAddress((void**)&qalo, g_qalo);
    cudaGetSymbolAddress((void**)&kv,   g_kv);
    cudaGetSymbolAddress((void**)&qhi,  g_qhi);
    cudaGetSymbolAddress((void**)&qlo,  g_qlo);
    cudaGetSymbolAddress((void**)&lg,   g_logits);
    cudaGetSymbolAddress((void**)&tau,  g_tau);
    cudaGetSymbolAddress((void**)&mr,   g_mrow);
    cudaGetSymbolAddress((void**)&iv,   g_invden);
    cudaGetSymbolAddress((void**)&op,   g_opart);
    cudaGetSymbolAddress((void**)&oohi, g_oohi);
    cudaGetSymbolAddress((void**)&oolo, g_oolo);
    cudaGetSymbolAddress((void**)&lathi,g_lathi);
    cudaGetSymbolAddress((void**)&latlo,g_latlo);
    cudaGetSymbolAddress((void**)&part, g_part);

    static cudaStream_t s1 = 0;
    static cudaEvent_t  e0 = 0, e1 = 0;
    if (!s1) {
        cudaStreamCreateWithFlags(&s1, cudaStreamNonBlocking);
        cudaEventCreateWithFlags(&e0, cudaEventDisableTiming);
        cudaEventCreateWithFlags(&e1, cudaEventDisableTiming);
        cudaFuncSetAttribute(k_gemm_mma,   cudaFuncAttributeMaxDynamicSharedMemorySize, MM_SMEM);
        cudaFuncSetAttribute(k_logits_mma, cudaFuncAttributeMaxDynamicSharedMemorySize, LG_SMEM);
        cudaFuncSetAttribute(k_accum_mma,  cudaFuncAttributeMaxDynamicSharedMemorySize, AC_SMEM);
        cudaFuncSetAttribute(k_gemm_mma,   cudaFuncAttributePreferredSharedMemoryCarveout, 50);
        cudaFuncSetAttribute(k_logits_mma, cudaFuncAttributePreferredSharedMemoryCarveout, 76);
        cudaFuncSetAttribute(k_accum_mma,  cudaFuncAttributePreferredSharedMemoryCarveout, 55);
    }

    /* ---- x -> bf16 hi/lo ---- */
    k_x2bf<<<NB*DIMX/512, 256>>>(x, xhi, xlo);
    cudaEventRecord(e0, 0);
    cudaStreamWaitEvent(s1, e0, 0);

    /* ---- branch A (stream 0): wq_a -> rms -> wq_b -> rope/split ---- */
    k_gemm_mma<<<dim3(12, 16, 1), 256, MM_SMEM>>>(
        xhi, xlo, DIMX, 0, wqa, DIMX, 0,
        part + PART_QA_OFF, QLRK, 0, (long long)NB*QLRK, 256, QLRK);
    k_fuse_qa<<<NB, 256>>>(part + PART_QA_OFF, qnw, qahi, qalo);
    k_gemm_mma<<<dim3(48, 6, 1), 256, MM_SMEM>>>(
        qahi, qalo, QLRK, 0, wqb, QLRK, 0,
        part + PART_QB_OFF, QDIM, 0, (long long)NB*QDIM, 256, QDIM);
    k_fuse_q<<<NB, 256>>>(part + PART_QB_OFF, ctxl, qhi, qlo);

    /* ---- branch B (stream s1): wkv -> rms+rope ---- */
    k_gemm_mma<<<dim3(2, 32, 1), 256, MM_SMEM, s1>>>(
        xhi, xlo, DIMX, 0, wkv, DIMX, 0,
        part + PART_KV_OFF, HDIM, 0, (long long)NB*HDIM, 128, HDIM);
    k_fuse_kv<<<NB, 64, 0, s1>>>(part + PART_KV_OFF, kvnw, ctxl, kv);
    cudaEventRecord(e1, s1);
    cudaStreamWaitEvent(0, e1, 0);

    /* ---- attention ---- */
    k_logits_mma<<<dim3(16, NB), 256, LG_SMEM>>>(kvc, bt, ctxl, qhi, qlo, kv, lg);
    k_select<<<NB*HEADS, 256>>>(lg, sink, ctxl, tau, mr, iv);
    k_accum_mma<<<dim3(8, NB), 256, AC_SMEM>>>(kvc, bt, ctxl, kv, lg, tau, mr, iv, op);
    k_reduce_o<<<NB*QDIM/512, 256>>>(op, oohi, oolo);

    /* ---- lat = grouped wo_a : split 12 ---- */
    k_gemm_mma<<<dim3(4, 12, GRP), 256, MM_SMEM>>>(
        oohi, oolo, QDIM, 768, woa, 768, (long long)OLRK*768,
        part, GRP*OLRK, OLRK, (long long)NB*GRP*OLRK, 64, OLRK);
    k_reduce_bf<<<(NB*GRP*OLRK/2+255)/256, 256>>>(part, lathi, latlo,
                                                  NB*GRP*OLRK/2, NB*GRP*OLRK, 12);

    /* ---- out = lat @ wo_b^T : split 16 ---- */
    k_gemm_mma<<<dim3(32, 16, 1), 256, MM_SMEM>>>(
        lathi, latlo, GRP*OLRK, 0, wob, DIMX, 0,
        part, DIMX, 0, (long long)NB*DIMX, 256, DIMX);
    k_reduce<<<(NB*DIMX+255)/256, 256>>>(part, out, NB*DIMX, 16);
}